// round 1
// baseline (speedup 1.0000x reference)
#include <cuda_runtime.h>
#include <math.h>

// Problem constants (fixed by reference)
#define NU_  100000
#define NI_  50000
#define NT_  150000
#define D_   64
#define NNZ_ 2400000
#define BRI_ 50000

// Scratch: 3 x [N, 64] float buffers + scalar accumulators + order flag.
__device__ float g_X[(size_t)NT_ * D_];
__device__ float g_Y[(size_t)NT_ * D_];
__device__ float g_acc[(size_t)NT_ * D_];
__device__ float g_scal[256];
// slot 0: rating sum; 1: sum logsig(u1@s_bri); 2: sum log(1-sig(u2@s_bri));
// 3: sum logsig(u1@i_bri); 4: sum log(1-sig(u2@i_bri));
// 8..71: column sums for g_soc; 72..135: g_iu sums; 136..199: g_ii sums
__device__ int g_ordB;

__device__ __forceinline__ float sp_(float x) {  // softplus
    return (x > 15.f) ? x : log1pf(expf(x));
}

// Zero scalar accumulators + detect input ordering by inspecting d_in[8]:
// ints < 150000 have bit patterns < 0x04000000; uniform floats don't.
__global__ void k_setup(const unsigned* __restrict__ p8) {
    int t = threadIdx.x;
    if (t < 256) g_scal[t] = 0.f;
    if (t == 0) {
        int fl = 0;
        for (int i = 0; i < 64; i++)
            if (p8[i] > 0x04000000u) fl++;
        g_ordB = (fl > 32) ? 1 : 0;
    }
}

// X = acc = concat(user_embed, item_embed); Y = 0
__global__ void __launch_bounds__(256) k_init(const float* __restrict__ eu,
                                              const float* __restrict__ ei) {
    int i = blockIdx.x * 256 + threadIdx.x;  // float4 index
    if (i >= NT_ * D_ / 4) return;
    int f = i * 4;
    float4 v = (f < NU_ * D_) ? *(const float4*)(eu + f)
                              : *(const float4*)(ei + (f - NU_ * D_));
    ((float4*)g_X)[i] = v;
    ((float4*)g_acc)[i] = v;
    ((float4*)g_Y)[i] = make_float4(0.f, 0.f, 0.f, 0.f);
}

// COO SpMM: y[r] += v * x[c], 16 threads per edge, float4 vector reductions.
// Two candidate (rows, cols, vals) triples; g_ordB selects at runtime.
__global__ void __launch_bounds__(256) k_spmm(
    const void* a0, const void* a1, const void* a2,
    const void* b0, const void* b1, const void* b2, int dir) {
    int tid = blockIdx.x * 256 + threadIdx.x;
    int e = tid >> 4;
    if (e >= NNZ_) return;
    int k = tid & 15;
    const int *rows, *cols;
    const float* vals;
    if (g_ordB) { rows = (const int*)b0; cols = (const int*)b1; vals = (const float*)b2; }
    else        { rows = (const int*)a0; cols = (const int*)a1; vals = (const float*)a2; }
    const float* x = dir ? g_Y : g_X;
    float* y = dir ? g_X : g_Y;
    int r = __ldg(rows + e);
    int c = __ldg(cols + e);
    float v = __ldg(vals + e);
    const float4 xv = *(const float4*)(x + c * D_ + k * 4);
    float* p = y + r * D_ + k * 4;
    asm volatile("red.relaxed.gpu.global.add.v4.f32 [%0], {%1,%2,%3,%4};"
                 :: "l"(p), "f"(v * xv.x), "f"(v * xv.y), "f"(v * xv.z), "f"(v * xv.w)
                 : "memory");
}

// s += h (new h); acc += s; h = 0 (next spmm target). dir: which buffer holds h.
__global__ void __launch_bounds__(256) k_fused(int dir) {
    int i = blockIdx.x * 256 + threadIdx.x;
    if (i >= NT_ * D_ / 4) return;
    float4* H = dir ? (float4*)g_Y : (float4*)g_X;
    float4* S = dir ? (float4*)g_X : (float4*)g_Y;
    float4 h = H[i];
    float4 s = S[i];
    float4 a = ((float4*)g_acc)[i];
    s.x += h.x; s.y += h.y; s.z += h.z; s.w += h.w;
    a.x += s.x; a.y += s.y; a.z += s.z; a.w += s.w;
    S[i] = s;
    ((float4*)g_acc)[i] = a;
    H[i] = make_float4(0.f, 0.f, 0.f, 0.f);
}

// BPR rating loss over 8192 triples; one warp per sample.
__global__ void __launch_bounds__(256) k_rating(const int* __restrict__ user,
                                                const int* __restrict__ pos,
                                                const int* __restrict__ neg) {
    int gt = blockIdx.x * 256 + threadIdx.x;
    int w = gt >> 5, lane = gt & 31;
    if (w >= 8192) return;
    int ur = user[w] * D_;
    int pr = (NU_ + pos[w]) * D_;
    int nr = (NU_ + neg[w]) * D_;
    float pp = 0.f, np = 0.f, l2 = 0.f;
#pragma unroll
    for (int q = 0; q < 2; q++) {
        int d = lane * 2 + q;
        float u = 0.25f * g_acc[ur + d];
        float a = 0.25f * g_acc[pr + d];
        float b = 0.25f * g_acc[nr + d];
        pp += u * a;
        np += u * b;
        l2 += u * u + a * a + b * b;
    }
    for (int o = 16; o; o >>= 1) {
        pp += __shfl_down_sync(0xffffffffu, pp, o);
        np += __shfl_down_sync(0xffffffffu, np, o);
        l2 += __shfl_down_sync(0xffffffffu, l2, o);
    }
    if (lane == 0) atomicAdd(&g_scal[0], sp_(np - pp) + 0.01f * l2);
}

// Sum of -softplus(sign*x) over 4096x64 gathered user rows -> g_scal[slot].
// sign=-1 => log sigmoid(x); sign=+1 => log(1 - sigmoid(x)).
__global__ void __launch_bounds__(256) k_brilog(const int* __restrict__ idx,
                                                float sign, int slot) {
    int t = blockIdx.x * 256 + threadIdx.x;  // exactly 4096*64 threads
    int i = t >> 6, d = t & 63;
    float x = 0.25f * g_acc[idx[i] * D_ + d];
    float val = -sp_(sign * x);
    __shared__ float sm[256];
    sm[threadIdx.x] = val;
    __syncthreads();
    for (int s = 128; s; s >>= 1) {
        if (threadIdx.x < s) sm[threadIdx.x] += sm[threadIdx.x + s];
        __syncthreads();
    }
    if (threadIdx.x == 0) atomicAdd(&g_scal[slot], sm[0]);
}

// Column sums of acc rows [BRI_, BRI_+50000) -> g_scal[8+d] (0.25, /50000 at end).
__global__ void __launch_bounds__(256) k_gsoc() {
    int gt = blockIdx.x * 256 + threadIdx.x;  // grid = 128 blocks -> 512 row groups
    int d = gt & 63;
    int rg = gt >> 6;
    float s = 0.f;
    for (int r = BRI_ + rg; r < BRI_ + 50000; r += 512) s += g_acc[r * D_ + d];
    __shared__ float sm[256];
    sm[threadIdx.x] = s;
    __syncthreads();
    if (threadIdx.x < 64)
        atomicAdd(&g_scal[8 + threadIdx.x],
                  sm[threadIdx.x] + sm[threadIdx.x + 64] +
                  sm[threadIdx.x + 128] + sm[threadIdx.x + 192]);
}

// Column sums of sigmoid(0.25*acc[rowoff+idx[i]]) over 4096 rows -> g_scal[slot+d].
__global__ void __launch_bounds__(256) k_gmean(const int* __restrict__ idx,
                                               int rowoff, int slot) {
    int t = blockIdx.x * 256 + threadIdx.x;  // exactly 4096*64 threads
    int i = t >> 6, d = t & 63;
    float x = 0.25f * g_acc[(rowoff + idx[i]) * D_ + d];
    float sg = 1.f / (1.f + expf(-x));
    __shared__ float sm[256];
    sm[threadIdx.x] = sg;
    __syncthreads();
    if (threadIdx.x < 64)
        atomicAdd(&g_scal[slot + threadIdx.x],
                  sm[threadIdx.x] + sm[threadIdx.x + 64] +
                  sm[threadIdx.x + 128] + sm[threadIdx.x + 192]);
}

// Combine everything into the 4 outputs.
__global__ void k_final(float* __restrict__ out) {
    double sgr = 0.0, sgf = 0.0, sir = 0.0, sif = 0.0;
    for (int d = 0; d < 64; d++) {
        double gs = 0.25 * (double)g_scal[8 + d] / 50000.0;
        double sg = 1.0 / (1.0 + exp(-gs));
        sgr += log(sg);
        sgf += log(1.0 - sg);
    }
    for (int d = 0; d < 128; d++) {
        double g = (double)g_scal[72 + d] / 4096.0;
        sir += log(g);
        sif += log1p(-g);
    }
    double A1 = g_scal[0], A2 = g_scal[1], A3 = g_scal[2];
    double A5 = g_scal[3], A6 = g_scal[4];
    double social = -(A2 / (4096.0 * 128.0) + sgr / 128.0)
                    - (A3 / (4096.0 * 128.0) + sgf / 128.0);
    double infor  = -(A5 / (4096.0 * 192.0) + sir / 192.0)
                    - (A6 / (4096.0 * 192.0) + sif / 192.0);
    double rating = A1;
    double obj = rating + 100.0 * social + 1000.0 * infor;
    out[0] = (float)obj;
    out[1] = (float)rating;
    out[2] = (float)social;
    out[3] = (float)infor;
}

extern "C" void kernel_launch(void* const* d_in, const int* in_sizes, int n_in,
                              void* d_out, int out_size) {
    const float* emb_u[4] = {(const float*)d_in[0], (const float*)d_in[2],
                             (const float*)d_in[4], (const float*)d_in[6]};
    const float* emb_i[4] = {(const float*)d_in[1], (const float*)d_in[3],
                             (const float*)d_in[5], (const float*)d_in[7]};
    const int* user      = (const int*)d_in[20];
    const int* pos       = (const int*)d_in[21];
    const int* neg       = (const int*)d_in[22];
    const int* s_bri     = (const int*)d_in[23];
    const int* i_bri     = (const int*)d_in[24];
    const int* i_bri_pos = (const int*)d_in[25];

    k_setup<<<1, 256>>>((const unsigned*)d_in[8]);

    const int EWG = (NT_ * D_ / 4 + 255) / 256;
    const int SPG = (NNZ_ * 16) / 256;

    for (int l = 0; l < 4; l++) {
        k_init<<<EWG, 256>>>(emb_u[l], emb_i[l]);
        for (int hop = 0; hop < 3; hop++) {
            int dir = hop & 1;
            // Ordering A (dict): r=d_in[8+3l], c=d_in[9+3l], v=d_in[10+3l]
            // Ordering B (sig):  v=d_in[8+l],  r=d_in[12+2l], c=d_in[13+2l]
            k_spmm<<<SPG, 256>>>(d_in[8 + 3 * l], d_in[9 + 3 * l], d_in[10 + 3 * l],
                                 d_in[12 + 2 * l], d_in[13 + 2 * l], d_in[8 + l], dir);
            k_fused<<<EWG, 256>>>(dir);
        }
        if (l == 0) {
            k_rating<<<1024, 256>>>(user, pos, neg);
            k_brilog<<<1024, 256>>>(s_bri, -1.f, 1);
            k_brilog<<<1024, 256>>>(i_bri, -1.f, 3);
        } else if (l == 1) {
            k_brilog<<<1024, 256>>>(s_bri, 1.f, 2);
            k_brilog<<<1024, 256>>>(i_bri, 1.f, 4);
        } else if (l == 2) {
            k_gsoc<<<128, 256>>>();
        } else {
            k_gmean<<<1024, 256>>>(i_bri, 0, 72);
            k_gmean<<<1024, 256>>>(i_bri_pos, NU_, 136);
        }
    }
    k_final<<<1, 1>>>((float*)d_out);
}

// round 2
// speedup vs baseline: 1.1068x; 1.1068x over previous
#include <cuda_runtime.h>
#include <math.h>

#define NU_  100000
#define NI_  50000
#define NT_  150000
#define D_   64
#define NNZ_ 2400000
#define BRI_ 50000

// Embedding scratch
__device__ float g_X[(size_t)NT_ * D_];
__device__ float g_Y[(size_t)NT_ * D_];
__device__ float g_acc[(size_t)NT_ * D_];
// CSR scratch (rebuilt per adjacency, reused across its 3 hops)
__device__ int  g_rowptr[NT_ + 1];
__device__ int  g_cnt[NT_];
__device__ int  g_pos[NT_];
__device__ int2 g_edges[NNZ_];   // (col, float_bits(val))
// Scalar accumulators + ordering flag
__device__ float g_scal[256];
__device__ int g_ordB;

__device__ __forceinline__ float sp_(float x) {  // softplus
    return (x > 15.f) ? x : log1pf(expf(x));
}

// ---------------------------------------------------------------------------
// Zero scalar accumulators + detect input ordering by inspecting d_in[8]:
// int32 node ids < 150000 have bit patterns < 0x04000000; uniform floats don't.
__global__ void k_setup(const unsigned* __restrict__ p8) {
    int t = threadIdx.x;
    if (t < 256) g_scal[t] = 0.f;
    if (t == 0) {
        int fl = 0;
        for (int i = 0; i < 64; i++)
            if (p8[i] > 0x04000000u) fl++;
        g_ordB = (fl > 32) ? 1 : 0;
    }
}

// X = acc = concat(user_embed, item_embed); also zero row-count histogram.
__global__ void __launch_bounds__(256) k_init(const float* __restrict__ eu,
                                              const float* __restrict__ ei) {
    int i = blockIdx.x * 256 + threadIdx.x;  // float4 index
    if (i >= NT_ * D_ / 4) return;
    if (i < NT_) g_cnt[i] = 0;
    int f = i * 4;
    float4 v = (f < NU_ * D_) ? *(const float4*)(eu + f)
                              : *(const float4*)(ei + (f - NU_ * D_));
    ((float4*)g_X)[i] = v;
    ((float4*)g_acc)[i] = v;
}

// Histogram of row ids.
__global__ void __launch_bounds__(256) k_hist(const void* a0, const void* b0) {
    int e = blockIdx.x * 256 + threadIdx.x;
    if (e >= NNZ_) return;
    const int* rows = g_ordB ? (const int*)b0 : (const int*)a0;
    atomicAdd(&g_cnt[rows[e]], 1);
}

// Single-block exclusive scan of g_cnt -> g_rowptr (and g_pos copy).
__global__ void __launch_bounds__(1024) k_scan() {
    __shared__ int sm[1024];
    const int CH = (NT_ + 1023) >> 10;  // 147
    int t = threadIdx.x;
    int b = t * CH;
    int e = min(b + CH, NT_);
    int s = 0;
    for (int i = b; i < e; i++) s += g_cnt[i];
    sm[t] = s;
    __syncthreads();
    for (int o = 1; o < 1024; o <<= 1) {
        int v = (t >= o) ? sm[t - o] : 0;
        __syncthreads();
        if (t >= o) sm[t] += v;
        __syncthreads();
    }
    int run = (t == 0) ? 0 : sm[t - 1];
    for (int i = b; i < e; i++) {
        g_rowptr[i] = run;
        g_pos[i] = run;
        run += g_cnt[i];
    }
    if (b < NT_ && e == NT_) g_rowptr[NT_] = run;
}

// Scatter edges into CSR slots (order within a row is arbitrary; fp-sum order
// differences are ~1e-7, far below the 1e-3 tolerance).
__global__ void __launch_bounds__(256) k_scatter(
    const void* a0, const void* a1, const void* a2,
    const void* b0, const void* b1, const void* b2) {
    int e = blockIdx.x * 256 + threadIdx.x;
    if (e >= NNZ_) return;
    const int *rows, *cols;
    const float* vals;
    if (g_ordB) { rows = (const int*)b0; cols = (const int*)b1; vals = (const float*)b2; }
    else        { rows = (const int*)a0; cols = (const int*)a1; vals = (const float*)a2; }
    int r = rows[e];
    int c = cols[e];
    float v = vals[e];
    int p = atomicAdd(&g_pos[r], 1);
    g_edges[p] = make_int2(c, __float_as_int(v));
}

// CSR SpMM + fused residual/accumulate epilogue.
// 16 threads per row (float4 lanes). Edge (c,v) loaded cooperatively, then
// broadcast across the 16-lane group with shfl. out = sum + h[row]; acc += out.
__global__ void __launch_bounds__(256) k_spmm_csr(int dir) {
    int tid = blockIdx.x * 256 + threadIdx.x;
    int row = tid >> 4;
    if (row >= NT_) return;
    int k = tid & 15;
    const float* x = dir ? g_Y : g_X;
    float* y = dir ? g_X : g_Y;
    int s0 = g_rowptr[row];
    int s1 = g_rowptr[row + 1];
    unsigned mask = 0xFFFFu << (threadIdx.x & 16);
    float4 s = make_float4(0.f, 0.f, 0.f, 0.f);
    for (int e = s0; e < s1; e += 16) {
        int n = min(16, s1 - e);
        int c = 0;
        float v = 0.f;
        if (k < n) {
            int2 ed = g_edges[e + k];
            c = ed.x;
            v = __int_as_float(ed.y);
        }
#pragma unroll 4
        for (int j = 0; j < n; j++) {
            int cj = __shfl_sync(mask, c, j, 16);
            float vj = __shfl_sync(mask, v, j, 16);
            const float4 xv = *(const float4*)(x + cj * D_ + k * 4);
            s.x += vj * xv.x;
            s.y += vj * xv.y;
            s.z += vj * xv.z;
            s.w += vj * xv.w;
        }
    }
    const float4 h = *(const float4*)(x + row * D_ + k * 4);
    s.x += h.x; s.y += h.y; s.z += h.z; s.w += h.w;
    *(float4*)(y + row * D_ + k * 4) = s;
    float4* ap = (float4*)(g_acc + row * D_ + k * 4);
    float4 a = *ap;
    a.x += s.x; a.y += s.y; a.z += s.z; a.w += s.w;
    *ap = a;
}

// ---------------------------------------------------------------------------
// Loss kernels (read g_acc, apply the 0.25 mean factor inline).

__global__ void __launch_bounds__(256) k_rating(const int* __restrict__ user,
                                                const int* __restrict__ pos,
                                                const int* __restrict__ neg) {
    int gt = blockIdx.x * 256 + threadIdx.x;
    int w = gt >> 5, lane = gt & 31;
    if (w >= 8192) return;
    int ur = user[w] * D_;
    int pr = (NU_ + pos[w]) * D_;
    int nr = (NU_ + neg[w]) * D_;
    float pp = 0.f, np = 0.f, l2 = 0.f;
#pragma unroll
    for (int q = 0; q < 2; q++) {
        int d = lane * 2 + q;
        float u = 0.25f * g_acc[ur + d];
        float a = 0.25f * g_acc[pr + d];
        float b = 0.25f * g_acc[nr + d];
        pp += u * a;
        np += u * b;
        l2 += u * u + a * a + b * b;
    }
    for (int o = 16; o; o >>= 1) {
        pp += __shfl_down_sync(0xffffffffu, pp, o);
        np += __shfl_down_sync(0xffffffffu, np, o);
        l2 += __shfl_down_sync(0xffffffffu, l2, o);
    }
    if (lane == 0) atomicAdd(&g_scal[0], sp_(np - pp) + 0.01f * l2);
}

__global__ void __launch_bounds__(256) k_brilog(const int* __restrict__ idx,
                                                float sign, int slot) {
    int t = blockIdx.x * 256 + threadIdx.x;  // exactly 4096*64 threads
    int i = t >> 6, d = t & 63;
    float x = 0.25f * g_acc[idx[i] * D_ + d];
    float val = -sp_(sign * x);
    __shared__ float sm[256];
    sm[threadIdx.x] = val;
    __syncthreads();
    for (int s = 128; s; s >>= 1) {
        if (threadIdx.x < s) sm[threadIdx.x] += sm[threadIdx.x + s];
        __syncthreads();
    }
    if (threadIdx.x == 0) atomicAdd(&g_scal[slot], sm[0]);
}

__global__ void __launch_bounds__(256) k_gsoc() {
    int gt = blockIdx.x * 256 + threadIdx.x;  // grid = 128 blocks -> 512 row groups
    int d = gt & 63;
    int rg = gt >> 6;
    float s = 0.f;
    for (int r = BRI_ + rg; r < BRI_ + 50000; r += 512) s += g_acc[r * D_ + d];
    __shared__ float sm[256];
    sm[threadIdx.x] = s;
    __syncthreads();
    if (threadIdx.x < 64)
        atomicAdd(&g_scal[8 + threadIdx.x],
                  sm[threadIdx.x] + sm[threadIdx.x + 64] +
                  sm[threadIdx.x + 128] + sm[threadIdx.x + 192]);
}

__global__ void __launch_bounds__(256) k_gmean(const int* __restrict__ idx,
                                               int rowoff, int slot) {
    int t = blockIdx.x * 256 + threadIdx.x;  // exactly 4096*64 threads
    int i = t >> 6, d = t & 63;
    float x = 0.25f * g_acc[(rowoff + idx[i]) * D_ + d];
    float sg = 1.f / (1.f + expf(-x));
    __shared__ float sm[256];
    sm[threadIdx.x] = sg;
    __syncthreads();
    if (threadIdx.x < 64)
        atomicAdd(&g_scal[slot + threadIdx.x],
                  sm[threadIdx.x] + sm[threadIdx.x + 64] +
                  sm[threadIdx.x + 128] + sm[threadIdx.x + 192]);
}

__global__ void k_final(float* __restrict__ out) {
    double sgr = 0.0, sgf = 0.0, sir = 0.0, sif = 0.0;
    for (int d = 0; d < 64; d++) {
        double gs = 0.25 * (double)g_scal[8 + d] / 50000.0;
        double sg = 1.0 / (1.0 + exp(-gs));
        sgr += log(sg);
        sgf += log(1.0 - sg);
    }
    for (int d = 0; d < 128; d++) {
        double g = (double)g_scal[72 + d] / 4096.0;
        sir += log(g);
        sif += log1p(-g);
    }
    double A1 = g_scal[0], A2 = g_scal[1], A3 = g_scal[2];
    double A5 = g_scal[3], A6 = g_scal[4];
    double social = -(A2 / (4096.0 * 128.0) + sgr / 128.0)
                    - (A3 / (4096.0 * 128.0) + sgf / 128.0);
    double infor  = -(A5 / (4096.0 * 192.0) + sir / 192.0)
                    - (A6 / (4096.0 * 192.0) + sif / 192.0);
    double rating = A1;
    double obj = rating + 100.0 * social + 1000.0 * infor;
    out[0] = (float)obj;
    out[1] = (float)rating;
    out[2] = (float)social;
    out[3] = (float)infor;
}

extern "C" void kernel_launch(void* const* d_in, const int* in_sizes, int n_in,
                              void* d_out, int out_size) {
    const float* emb_u[4] = {(const float*)d_in[0], (const float*)d_in[2],
                             (const float*)d_in[4], (const float*)d_in[6]};
    const float* emb_i[4] = {(const float*)d_in[1], (const float*)d_in[3],
                             (const float*)d_in[5], (const float*)d_in[7]};
    const int* user      = (const int*)d_in[20];
    const int* pos       = (const int*)d_in[21];
    const int* neg       = (const int*)d_in[22];
    const int* s_bri     = (const int*)d_in[23];
    const int* i_bri     = (const int*)d_in[24];
    const int* i_bri_pos = (const int*)d_in[25];

    k_setup<<<1, 256>>>((const unsigned*)d_in[8]);

    const int EWG = (NT_ * D_ / 4 + 255) / 256;   // 9375
    const int EDG = (NNZ_ + 255) / 256;           // 9375
    const int SPG = (NT_ * 16 + 255) / 256;       // 9375

    for (int l = 0; l < 4; l++) {
        // Ordering A (dict): r=d_in[8+3l], c=d_in[9+3l], v=d_in[10+3l]
        // Ordering B (sig):  v=d_in[8+l],  r=d_in[12+2l], c=d_in[13+2l]
        k_init<<<EWG, 256>>>(emb_u[l], emb_i[l]);
        k_hist<<<EDG, 256>>>(d_in[8 + 3 * l], d_in[12 + 2 * l]);
        k_scan<<<1, 1024>>>();
        k_scatter<<<EDG, 256>>>(d_in[8 + 3 * l], d_in[9 + 3 * l], d_in[10 + 3 * l],
                                d_in[12 + 2 * l], d_in[13 + 2 * l], d_in[8 + l]);
        for (int hop = 0; hop < 3; hop++) {
            k_spmm_csr<<<SPG, 256>>>(hop & 1);
        }
        if (l == 0) {
            k_rating<<<1024, 256>>>(user, pos, neg);
            k_brilog<<<1024, 256>>>(s_bri, -1.f, 1);
            k_brilog<<<1024, 256>>>(i_bri, -1.f, 3);
        } else if (l == 1) {
            k_brilog<<<1024, 256>>>(s_bri, 1.f, 2);
            k_brilog<<<1024, 256>>>(i_bri, 1.f, 4);
        } else if (l == 2) {
            k_gsoc<<<128, 256>>>();
        } else {
            k_gmean<<<1024, 256>>>(i_bri, 0, 72);
            k_gmean<<<1024, 256>>>(i_bri_pos, NU_, 136);
        }
    }
    k_final<<<1, 1>>>((float*)d_out);
}

// round 4
// speedup vs baseline: 1.7726x; 1.6015x over previous
#include <cuda_runtime.h>
#include <math.h>

#define NU_  100000
#define NI_  50000
#define NT_  150000
#define D_   64
#define NNZ_ 2400000
#define BRI_ 50000
#define SCB_ 147            // scan blocks: ceil(150000/1024)

// Embedding scratch
__device__ float g_X[(size_t)NT_ * D_];
__device__ float g_Y[(size_t)NT_ * D_];
__device__ float g_acc[(size_t)NT_ * D_];
// CSR scratch (rebuilt per adjacency, reused across its 3 hops)
__device__ int  g_rowptr[NT_ + 1];
__device__ int  g_cnt[NT_];
__device__ int  g_pos[NT_];
__device__ int2 g_edges[NNZ_];   // (col, float_bits(val))
__device__ int  g_bsum[SCB_];
__device__ int  g_boff[SCB_];
// Scalar accumulators + ordering flag
__device__ float g_scal[256];
__device__ int g_ordB;

__device__ __forceinline__ float sp_(float x) {  // softplus
    return (x > 15.f) ? x : log1pf(expf(x));
}

// ---------------------------------------------------------------------------
// Zero scalar accumulators + detect input ordering by inspecting d_in[8]:
// int32 node ids < 150000 have bit patterns < 0x04000000; uniform floats don't.
__global__ void k_setup(const unsigned* __restrict__ p8) {
    int t = threadIdx.x;
    if (t < 256) g_scal[t] = 0.f;
    if (t == 0) {
        int fl = 0;
        for (int i = 0; i < 64; i++)
            if (p8[i] > 0x04000000u) fl++;
        g_ordB = (fl > 32) ? 1 : 0;
    }
}

// X = acc = concat(user_embed, item_embed); also zero row-count histogram.
__global__ void __launch_bounds__(256) k_init(const float* __restrict__ eu,
                                              const float* __restrict__ ei) {
    int i = blockIdx.x * 256 + threadIdx.x;  // float4 index
    if (i >= NT_ * D_ / 4) return;
    if (i < NT_) g_cnt[i] = 0;
    int f = i * 4;
    float4 v = (f < NU_ * D_) ? *(const float4*)(eu + f)
                              : *(const float4*)(ei + (f - NU_ * D_));
    ((float4*)g_X)[i] = v;
    ((float4*)g_acc)[i] = v;
}

// Histogram of row ids.
__global__ void __launch_bounds__(256) k_hist(const void* a0, const void* b0) {
    int e = blockIdx.x * 256 + threadIdx.x;
    if (e >= NNZ_) return;
    const int* rows = g_ordB ? (const int*)b0 : (const int*)a0;
    atomicAdd(&g_cnt[rows[e]], 1);
}

// Multi-block scan, phase A: per-block sums of g_cnt.
__global__ void __launch_bounds__(1024) k_scanA() {
    __shared__ int sm[1024];
    int t = threadIdx.x;
    int i = blockIdx.x * 1024 + t;
    sm[t] = (i < NT_) ? g_cnt[i] : 0;
    __syncthreads();
    for (int s = 512; s; s >>= 1) {
        if (t < s) sm[t] += sm[t + s];
        __syncthreads();
    }
    if (t == 0) g_bsum[blockIdx.x] = sm[0];
}

// Phase B: single small block scans the 147 block sums (exclusive).
__global__ void __launch_bounds__(256) k_scanB() {
    __shared__ int sm[256];
    int t = threadIdx.x;
    int v = (t < SCB_) ? g_bsum[t] : 0;
    sm[t] = v;
    __syncthreads();
    for (int o = 1; o < 256; o <<= 1) {
        int u = (t >= o) ? sm[t - o] : 0;
        __syncthreads();
        sm[t] += u;
        __syncthreads();
    }
    if (t < SCB_) g_boff[t] = sm[t] - v;
}

// Phase C: per-block local scan + global offset -> rowptr, pos.
__global__ void __launch_bounds__(1024) k_scanC() {
    __shared__ int sm[1024];
    int t = threadIdx.x;
    int i = blockIdx.x * 1024 + t;
    int v = (i < NT_) ? g_cnt[i] : 0;
    sm[t] = v;
    __syncthreads();
    for (int o = 1; o < 1024; o <<= 1) {
        int u = (t >= o) ? sm[t - o] : 0;
        __syncthreads();
        sm[t] += u;
        __syncthreads();
    }
    int excl = g_boff[blockIdx.x] + sm[t] - v;
    if (i < NT_) {
        g_rowptr[i] = excl;
        g_pos[i] = excl;
    }
    if (i == NT_ - 1) g_rowptr[NT_] = excl + v;
}

// Scatter edges into CSR slots (order within a row is arbitrary; fp-sum order
// differences are ~1e-7, far below the 1e-3 tolerance).
__global__ void __launch_bounds__(256) k_scatter(
    const void* a0, const void* a1, const void* a2,
    const void* b0, const void* b1, const void* b2) {
    int e = blockIdx.x * 256 + threadIdx.x;
    if (e >= NNZ_) return;
    const int *rows, *cols;
    const float* vals;
    if (g_ordB) { rows = (const int*)b0; cols = (const int*)b1; vals = (const float*)b2; }
    else        { rows = (const int*)a0; cols = (const int*)a1; vals = (const float*)a2; }
    int r = rows[e];
    int c = cols[e];
    float v = vals[e];
    int p = atomicAdd(&g_pos[r], 1);
    g_edges[p] = make_int2(c, __float_as_int(v));
}

// CSR SpMM + fused residual/accumulate epilogue.
// 16 threads per row (float4 lanes). Edge (c,v) loaded cooperatively, then
// broadcast across the 16-lane group with shfl. out = sum + h[row]; acc += out.
__global__ void __launch_bounds__(256) k_spmm_csr(int dir) {
    int tid = blockIdx.x * 256 + threadIdx.x;
    int row = tid >> 4;
    if (row >= NT_) return;
    int k = tid & 15;
    const float* x = dir ? g_Y : g_X;
    float* y = dir ? g_X : g_Y;
    int s0 = g_rowptr[row];
    int s1 = g_rowptr[row + 1];
    unsigned mask = 0xFFFFu << (threadIdx.x & 16);
    float4 s = make_float4(0.f, 0.f, 0.f, 0.f);
    for (int e = s0; e < s1; e += 16) {
        int n = min(16, s1 - e);
        int c = 0;
        float v = 0.f;
        if (k < n) {
            int2 ed = g_edges[e + k];
            c = ed.x;
            v = __int_as_float(ed.y);
        }
#pragma unroll 4
        for (int j = 0; j < n; j++) {
            int cj = __shfl_sync(mask, c, j, 16);
            float vj = __shfl_sync(mask, v, j, 16);
            const float4 xv = *(const float4*)(x + cj * D_ + k * 4);
            s.x += vj * xv.x;
            s.y += vj * xv.y;
            s.z += vj * xv.z;
            s.w += vj * xv.w;
        }
    }
    const float4 h = *(const float4*)(x + row * D_ + k * 4);
    s.x += h.x; s.y += h.y; s.z += h.z; s.w += h.w;
    *(float4*)(y + row * D_ + k * 4) = s;
    float4* ap = (float4*)(g_acc + row * D_ + k * 4);
    float4 a = *ap;
    a.x += s.x; a.y += s.y; a.z += s.z; a.w += s.w;
    *ap = a;
}

// ---------------------------------------------------------------------------
// Loss kernels (read g_acc, apply the 0.25 mean factor inline).

__global__ void __launch_bounds__(256) k_rating(const int* __restrict__ user,
                                                const int* __restrict__ pos,
                                                const int* __restrict__ neg) {
    int gt = blockIdx.x * 256 + threadIdx.x;
    int w = gt >> 5, lane = gt & 31;
    if (w >= 8192) return;
    int ur = user[w] * D_;
    int pr = (NU_ + pos[w]) * D_;
    int nr = (NU_ + neg[w]) * D_;
    float pp = 0.f, np = 0.f, l2 = 0.f;
#pragma unroll
    for (int q = 0; q < 2; q++) {
        int d = lane * 2 + q;
        float u = 0.25f * g_acc[ur + d];
        float a = 0.25f * g_acc[pr + d];
        float b = 0.25f * g_acc[nr + d];
        pp += u * a;
        np += u * b;
        l2 += u * u + a * a + b * b;
    }
    for (int o = 16; o; o >>= 1) {
        pp += __shfl_down_sync(0xffffffffu, pp, o);
        np += __shfl_down_sync(0xffffffffu, np, o);
        l2 += __shfl_down_sync(0xffffffffu, l2, o);
    }
    if (lane == 0) atomicAdd(&g_scal[0], sp_(np - pp) + 0.01f * l2);
}

__global__ void __launch_bounds__(256) k_brilog(const int* __restrict__ idx,
                                                float sign, int slot) {
    int t = blockIdx.x * 256 + threadIdx.x;  // exactly 4096*64 threads
    int i = t >> 6, d = t & 63;
    float x = 0.25f * g_acc[idx[i] * D_ + d];
    float val = -sp_(sign * x);
    __shared__ float sm[256];
    sm[threadIdx.x] = val;
    __syncthreads();
    for (int s = 128; s; s >>= 1) {
        if (threadIdx.x < s) sm[threadIdx.x] += sm[threadIdx.x + s];
        __syncthreads();
    }
    if (threadIdx.x == 0) atomicAdd(&g_scal[slot], sm[0]);
}

__global__ void __launch_bounds__(256) k_gsoc() {
    int gt = blockIdx.x * 256 + threadIdx.x;  // grid = 128 blocks -> 512 row groups
    int d = gt & 63;
    int rg = gt >> 6;
    float s = 0.f;
    for (int r = BRI_ + rg; r < BRI_ + 50000; r += 512) s += g_acc[r * D_ + d];
    __shared__ float sm[256];
    sm[threadIdx.x] = s;
    __syncthreads();
    if (threadIdx.x < 64)
        atomicAdd(&g_scal[8 + threadIdx.x],
                  sm[threadIdx.x] + sm[threadIdx.x + 64] +
                  sm[threadIdx.x + 128] + sm[threadIdx.x + 192]);
}

__global__ void __launch_bounds__(256) k_gmean(const int* __restrict__ idx,
                                               int rowoff, int slot) {
    int t = blockIdx.x * 256 + threadIdx.x;  // exactly 4096*64 threads
    int i = t >> 6, d = t & 63;
    float x = 0.25f * g_acc[(rowoff + idx[i]) * D_ + d];
    float sg = 1.f / (1.f + expf(-x));
    __shared__ float sm[256];
    sm[threadIdx.x] = sg;
    __syncthreads();
    if (threadIdx.x < 64)
        atomicAdd(&g_scal[slot + threadIdx.x],
                  sm[threadIdx.x] + sm[threadIdx.x + 64] +
                  sm[threadIdx.x + 128] + sm[threadIdx.x + 192]);
}

__global__ void k_final(float* __restrict__ out) {
    double sgr = 0.0, sgf = 0.0, sir = 0.0, sif = 0.0;
    for (int d = 0; d < 64; d++) {
        double gs = 0.25 * (double)g_scal[8 + d] / 50000.0;
        double sg = 1.0 / (1.0 + exp(-gs));
        sgr += log(sg);
        sgf += log(1.0 - sg);
    }
    for (int d = 0; d < 128; d++) {
        double g = (double)g_scal[72 + d] / 4096.0;
        sir += log(g);
        sif += log1p(-g);
    }
    double A1 = g_scal[0], A2 = g_scal[1], A3 = g_scal[2];
    double A5 = g_scal[3], A6 = g_scal[4];
    double social = -(A2 / (4096.0 * 128.0) + sgr / 128.0)
                    - (A3 / (4096.0 * 128.0) + sgf / 128.0);
    double infor  = -(A5 / (4096.0 * 192.0) + sir / 192.0)
                    - (A6 / (4096.0 * 192.0) + sif / 192.0);
    double rating = A1;
    double obj = rating + 100.0 * social + 1000.0 * infor;
    out[0] = (float)obj;
    out[1] = (float)rating;
    out[2] = (float)social;
    out[3] = (float)infor;
}

extern "C" void kernel_launch(void* const* d_in, const int* in_sizes, int n_in,
                              void* d_out, int out_size) {
    const float* emb_u[4] = {(const float*)d_in[0], (const float*)d_in[2],
                             (const float*)d_in[4], (const float*)d_in[6]};
    const float* emb_i[4] = {(const float*)d_in[1], (const float*)d_in[3],
                             (const float*)d_in[5], (const float*)d_in[7]};
    const int* user      = (const int*)d_in[20];
    const int* pos       = (const int*)d_in[21];
    const int* neg       = (const int*)d_in[22];
    const int* s_bri     = (const int*)d_in[23];
    const int* i_bri     = (const int*)d_in[24];
    const int* i_bri_pos = (const int*)d_in[25];

    k_setup<<<1, 256>>>((const unsigned*)d_in[8]);

    const int EWG = (NT_ * D_ / 4 + 255) / 256;   // 9375
    const int EDG = (NNZ_ + 255) / 256;           // 9375
    const int SPG = (NT_ * 16 + 255) / 256;       // 9375

    for (int l = 0; l < 4; l++) {
        // Ordering A (dict): r=d_in[8+3l], c=d_in[9+3l], v=d_in[10+3l]
        // Ordering B (sig):  v=d_in[8+l],  r=d_in[12+2l], c=d_in[13+2l]
        k_init<<<EWG, 256>>>(emb_u[l], emb_i[l]);
        k_hist<<<EDG, 256>>>(d_in[8 + 3 * l], d_in[12 + 2 * l]);
        k_scanA<<<SCB_, 1024>>>();
        k_scanB<<<1, 256>>>();
        k_scanC<<<SCB_, 1024>>>();
        k_scatter<<<EDG, 256>>>(d_in[8 + 3 * l], d_in[9 + 3 * l], d_in[10 + 3 * l],
                                d_in[12 + 2 * l], d_in[13 + 2 * l], d_in[8 + l]);
        for (int hop = 0; hop < 3; hop++) {
            k_spmm_csr<<<SPG, 256>>>(hop & 1);
        }
        if (l == 0) {
            k_rating<<<1024, 256>>>(user, pos, neg);
            k_brilog<<<1024, 256>>>(s_bri, -1.f, 1);
            k_brilog<<<1024, 256>>>(i_bri, -1.f, 3);
        } else if (l == 1) {
            k_brilog<<<1024, 256>>>(s_bri, 1.f, 2);
            k_brilog<<<1024, 256>>>(i_bri, 1.f, 4);
        } else if (l == 2) {
            k_gsoc<<<128, 256>>>();
        } else {
            k_gmean<<<1024, 256>>>(i_bri, 0, 72);
            k_gmean<<<1024, 256>>>(i_bri_pos, NU_, 136);
        }
    }
    k_final<<<1, 1>>>((float*)d_out);
}

// round 7
// speedup vs baseline: 1.9960x; 1.1260x over previous
#include <cuda_runtime.h>
#include <cuda_bf16.h>
#include <math.h>

#define NU_  100000
#define NI_  50000
#define NT_  150000
#define D_   64
#define NNZ_ 2400000
#define BRI_ 50000
#define SCB_ 147            // scan blocks: ceil(150000/1024)

// Propagation buffers in bf16 (halves gather traffic); accumulator in fp32.
__device__ __nv_bfloat16 g_Xh[(size_t)NT_ * D_];
__device__ __nv_bfloat16 g_Yh[(size_t)NT_ * D_];
__device__ float g_acc[(size_t)NT_ * D_];
// CSR scratch (rebuilt per adjacency, reused across its 3 hops)
__device__ int  g_rowptr[NT_ + 1];
__device__ int  g_cnt[NT_];
__device__ int  g_pos[NT_];
__device__ int2 g_edges[NNZ_];   // (col, float_bits(val))
__device__ int  g_bsum[SCB_];
__device__ int  g_boff[SCB_];
// Scalar accumulators + ordering flag
__device__ float g_scal[256];
__device__ int g_ordB;

__device__ __forceinline__ float sp_(float x) {  // softplus
    return (x > 15.f) ? x : log1pf(expf(x));
}

// ---------------------------------------------------------------------------
// Zero scalar accumulators + detect input ordering by inspecting d_in[8]:
// int32 node ids < 150000 have bit patterns < 0x04000000; uniform floats don't.
__global__ void k_setup(const unsigned* __restrict__ p8) {
    int t = threadIdx.x;
    if (t < 256) g_scal[t] = 0.f;
    if (t == 0) {
        int fl = 0;
        for (int i = 0; i < 64; i++)
            if (p8[i] > 0x04000000u) fl++;
        g_ordB = (fl > 32) ? 1 : 0;
    }
}

// X(bf16) = acc(fp32) = concat(user_embed, item_embed); zero histogram.
__global__ void __launch_bounds__(256) k_init(const float* __restrict__ eu,
                                              const float* __restrict__ ei) {
    int i = blockIdx.x * 256 + threadIdx.x;  // 8-float chunk index
    if (i >= NT_ * D_ / 8) return;
    if (i < NT_) g_cnt[i] = 0;
    int f = i * 8;
    const float* src = (f < NU_ * D_) ? (eu + f) : (ei + (f - NU_ * D_));
    float4 a = *(const float4*)(src);
    float4 b = *(const float4*)(src + 4);
    ((float4*)g_acc)[i * 2]     = a;
    ((float4*)g_acc)[i * 2 + 1] = b;
    __nv_bfloat162 h[4];
    h[0] = __float22bfloat162_rn(make_float2(a.x, a.y));
    h[1] = __float22bfloat162_rn(make_float2(a.z, a.w));
    h[2] = __float22bfloat162_rn(make_float2(b.x, b.y));
    h[3] = __float22bfloat162_rn(make_float2(b.z, b.w));
    *(uint4*)(g_Xh + f) = *(uint4*)h;
}

// Histogram of row ids.
__global__ void __launch_bounds__(256) k_hist(const void* a0, const void* b0) {
    int e = blockIdx.x * 256 + threadIdx.x;
    if (e >= NNZ_) return;
    const int* rows = g_ordB ? (const int*)b0 : (const int*)a0;
    atomicAdd(&g_cnt[rows[e]], 1);
}

// Multi-block scan, phase A: per-block sums of g_cnt.
__global__ void __launch_bounds__(1024) k_scanA() {
    __shared__ int sm[1024];
    int t = threadIdx.x;
    int i = blockIdx.x * 1024 + t;
    sm[t] = (i < NT_) ? g_cnt[i] : 0;
    __syncthreads();
    for (int s = 512; s; s >>= 1) {
        if (t < s) sm[t] += sm[t + s];
        __syncthreads();
    }
    if (t == 0) g_bsum[blockIdx.x] = sm[0];
}

// Phase B: single small block scans the 147 block sums (exclusive).
__global__ void __launch_bounds__(256) k_scanB() {
    __shared__ int sm[256];
    int t = threadIdx.x;
    int v = (t < SCB_) ? g_bsum[t] : 0;
    sm[t] = v;
    __syncthreads();
    for (int o = 1; o < 256; o <<= 1) {
        int u = (t >= o) ? sm[t - o] : 0;
        __syncthreads();
        sm[t] += u;
        __syncthreads();
    }
    if (t < SCB_) g_boff[t] = sm[t] - v;
}

// Phase C: per-block local scan + global offset -> rowptr, pos.
__global__ void __launch_bounds__(1024) k_scanC() {
    __shared__ int sm[1024];
    int t = threadIdx.x;
    int i = blockIdx.x * 1024 + t;
    int v = (i < NT_) ? g_cnt[i] : 0;
    sm[t] = v;
    __syncthreads();
    for (int o = 1; o < 1024; o <<= 1) {
        int u = (t >= o) ? sm[t - o] : 0;
        __syncthreads();
        sm[t] += u;
        __syncthreads();
    }
    int excl = g_boff[blockIdx.x] + sm[t] - v;
    if (i < NT_) {
        g_rowptr[i] = excl;
        g_pos[i] = excl;
    }
    if (i == NT_ - 1) g_rowptr[NT_] = excl + v;
}

// Scatter edges into CSR slots (fp-sum order nondeterminism ~1e-7, tol 1e-3).
__global__ void __launch_bounds__(256) k_scatter(
    const void* a0, const void* a1, const void* a2,
    const void* b0, const void* b1, const void* b2) {
    int e = blockIdx.x * 256 + threadIdx.x;
    if (e >= NNZ_) return;
    const int *rows, *cols;
    const float* vals;
    if (g_ordB) { rows = (const int*)b0; cols = (const int*)b1; vals = (const float*)b2; }
    else        { rows = (const int*)a0; cols = (const int*)a1; vals = (const float*)a2; }
    int r = rows[e];
    int c = cols[e];
    float v = vals[e];
    int p = atomicAdd(&g_pos[r], 1);
    g_edges[p] = make_int2(c, __float_as_int(v));
}

// CSR SpMM (bf16 x -> fp32 regs -> bf16 y) + fused residual/acc epilogue.
// 8 threads per row; each lane covers 8 dims (one 16B bf16 load per edge).
__global__ void __launch_bounds__(256) k_spmm_csr(int dir) {
    int tid = blockIdx.x * 256 + threadIdx.x;
    int row = tid >> 3;
    if (row >= NT_) return;
    int k = tid & 7;
    const __nv_bfloat16* x = dir ? g_Yh : g_Xh;
    __nv_bfloat16* y = dir ? g_Xh : g_Yh;
    int s0 = g_rowptr[row];
    int s1 = g_rowptr[row + 1];
    unsigned mask = 0xFFu << (threadIdx.x & 24);
    float s[8] = {0.f, 0.f, 0.f, 0.f, 0.f, 0.f, 0.f, 0.f};
    for (int e = s0; e < s1; e += 8) {
        int n = min(8, s1 - e);
        int c = 0;
        float v = 0.f;
        if (k < n) {
            int2 ed = g_edges[e + k];
            c = ed.x;
            v = __int_as_float(ed.y);
        }
#pragma unroll
        for (int j = 0; j < 8; j++) {
            if (j >= n) break;
            int cj = __shfl_sync(mask, c, j, 8);
            float vj = __shfl_sync(mask, v, j, 8);
            uint4 raw = *(const uint4*)(x + cj * D_ + k * 8);
            const __nv_bfloat162* p = (const __nv_bfloat162*)&raw;
#pragma unroll
            for (int q = 0; q < 4; q++) {
                float2 f = __bfloat1622float2(p[q]);
                s[q * 2]     += vj * f.x;
                s[q * 2 + 1] += vj * f.y;
            }
        }
    }
    // residual: + h[row]
    {
        uint4 raw = *(const uint4*)(x + row * D_ + k * 8);
        const __nv_bfloat162* p = (const __nv_bfloat162*)&raw;
#pragma unroll
        for (int q = 0; q < 4; q++) {
            float2 f = __bfloat1622float2(p[q]);
            s[q * 2]     += f.x;
            s[q * 2 + 1] += f.y;
        }
    }
    // store y (bf16)
    {
        __nv_bfloat162 h[4];
#pragma unroll
        for (int q = 0; q < 4; q++)
            h[q] = __float22bfloat162_rn(make_float2(s[q * 2], s[q * 2 + 1]));
        *(uint4*)(y + row * D_ + k * 8) = *(uint4*)h;
    }
    // acc += s (fp32)
    {
        float4* ap = (float4*)(g_acc + row * D_ + k * 8);
        float4 a0 = ap[0], a1 = ap[1];
        a0.x += s[0]; a0.y += s[1]; a0.z += s[2]; a0.w += s[3];
        a1.x += s[4]; a1.y += s[5]; a1.z += s[6]; a1.w += s[7];
        ap[0] = a0; ap[1] = a1;
    }
}

// ---------------------------------------------------------------------------
// Loss kernels (read g_acc, apply the 0.25 mean factor inline).

__global__ void __launch_bounds__(256) k_rating(const int* __restrict__ user,
                                                const int* __restrict__ pos,
                                                const int* __restrict__ neg) {
    int gt = blockIdx.x * 256 + threadIdx.x;
    int w = gt >> 5, lane = gt & 31;
    if (w >= 8192) return;
    int ur = user[w] * D_;
    int pr = (NU_ + pos[w]) * D_;
    int nr = (NU_ + neg[w]) * D_;
    float pp = 0.f, np = 0.f, l2 = 0.f;
#pragma unroll
    for (int q = 0; q < 2; q++) {
        int d = lane * 2 + q;
        float u = 0.25f * g_acc[ur + d];
        float a = 0.25f * g_acc[pr + d];
        float b = 0.25f * g_acc[nr + d];
        pp += u * a;
        np += u * b;
        l2 += u * u + a * a + b * b;
    }
    for (int o = 16; o; o >>= 1) {
        pp += __shfl_down_sync(0xffffffffu, pp, o);
        np += __shfl_down_sync(0xffffffffu, np, o);
        l2 += __shfl_down_sync(0xffffffffu, l2, o);
    }
    if (lane == 0) atomicAdd(&g_scal[0], sp_(np - pp) + 0.01f * l2);
}

__global__ void __launch_bounds__(256) k_brilog(const int* __restrict__ idx,
                                                float sign, int slot) {
    int t = blockIdx.x * 256 + threadIdx.x;  // exactly 4096*64 threads
    int i = t >> 6, d = t & 63;
    float x = 0.25f * g_acc[idx[i] * D_ + d];
    float val = -sp_(sign * x);
    __shared__ float sm[256];
    sm[threadIdx.x] = val;
    __syncthreads();
    for (int s = 128; s; s >>= 1) {
        if (threadIdx.x < s) sm[threadIdx.x] += sm[threadIdx.x + s];
        __syncthreads();
    }
    if (threadIdx.x == 0) atomicAdd(&g_scal[slot], sm[0]);
}

__global__ void __launch_bounds__(256) k_gsoc() {
    int gt = blockIdx.x * 256 + threadIdx.x;  // grid = 128 blocks -> 512 row groups
    int d = gt & 63;
    int rg = gt >> 6;
    float s = 0.f;
    for (int r = BRI_ + rg; r < BRI_ + 50000; r += 512) s += g_acc[r * D_ + d];
    __shared__ float sm[256];
    sm[threadIdx.x] = s;
    __syncthreads();
    if (threadIdx.x < 64)
        atomicAdd(&g_scal[8 + threadIdx.x],
                  sm[threadIdx.x] + sm[threadIdx.x + 64] +
                  sm[threadIdx.x + 128] + sm[threadIdx.x + 192]);
}

__global__ void __launch_bounds__(256) k_gmean(const int* __restrict__ idx,
                                               int rowoff, int slot) {
    int t = blockIdx.x * 256 + threadIdx.x;  // exactly 4096*64 threads
    int i = t >> 6, d = t & 63;
    float x = 0.25f * g_acc[(rowoff + idx[i]) * D_ + d];
    float sg = 1.f / (1.f + expf(-x));
    __shared__ float sm[256];
    sm[threadIdx.x] = sg;
    __syncthreads();
    if (threadIdx.x < 64)
        atomicAdd(&g_scal[slot + threadIdx.x],
                  sm[threadIdx.x] + sm[threadIdx.x + 64] +
                  sm[threadIdx.x + 128] + sm[threadIdx.x + 192]);
}

__global__ void k_final(float* __restrict__ out) {
    double sgr = 0.0, sgf = 0.0, sir = 0.0, sif = 0.0;
    for (int d = 0; d < 64; d++) {
        double gs = 0.25 * (double)g_scal[8 + d] / 50000.0;
        double sg = 1.0 / (1.0 + exp(-gs));
        sgr += log(sg);
        sgf += log(1.0 - sg);
    }
    for (int d = 0; d < 128; d++) {
        double g = (double)g_scal[72 + d] / 4096.0;
        sir += log(g);
        sif += log1p(-g);
    }
    double A1 = g_scal[0], A2 = g_scal[1], A3 = g_scal[2];
    double A5 = g_scal[3], A6 = g_scal[4];
    double social = -(A2 / (4096.0 * 128.0) + sgr / 128.0)
                    - (A3 / (4096.0 * 128.0) + sgf / 128.0);
    double infor  = -(A5 / (4096.0 * 192.0) + sir / 192.0)
                    - (A6 / (4096.0 * 192.0) + sif / 192.0);
    double rating = A1;
    double obj = rating + 100.0 * social + 1000.0 * infor;
    out[0] = (float)obj;
    out[1] = (float)rating;
    out[2] = (float)social;
    out[3] = (float)infor;
}

extern "C" void kernel_launch(void* const* d_in, const int* in_sizes, int n_in,
                              void* d_out, int out_size) {
    const float* emb_u[4] = {(const float*)d_in[0], (const float*)d_in[2],
                             (const float*)d_in[4], (const float*)d_in[6]};
    const float* emb_i[4] = {(const float*)d_in[1], (const float*)d_in[3],
                             (const float*)d_in[5], (const float*)d_in[7]};
    const int* user      = (const int*)d_in[20];
    const int* pos       = (const int*)d_in[21];
    const int* neg       = (const int*)d_in[22];
    const int* s_bri     = (const int*)d_in[23];
    const int* i_bri     = (const int*)d_in[24];
    const int* i_bri_pos = (const int*)d_in[25];

    k_setup<<<1, 256>>>((const unsigned*)d_in[8]);

    const int CHG = (NT_ * D_ / 8 + 255) / 256;   // 4688 (8-float chunks)
    const int EDG = (NNZ_ + 255) / 256;           // 9375
    const int SPG = (NT_ * 8 + 255) / 256;        // 4688

    for (int l = 0; l < 4; l++) {
        // Ordering A (dict): r=d_in[8+3l], c=d_in[9+3l], v=d_in[10+3l]
        // Ordering B (sig):  v=d_in[8+l],  r=d_in[12+2l], c=d_in[13+2l]
        k_init<<<CHG, 256>>>(emb_u[l], emb_i[l]);
        k_hist<<<EDG, 256>>>(d_in[8 + 3 * l], d_in[12 + 2 * l]);
        k_scanA<<<SCB_, 1024>>>();
        k_scanB<<<1, 256>>>();
        k_scanC<<<SCB_, 1024>>>();
        k_scatter<<<EDG, 256>>>(d_in[8 + 3 * l], d_in[9 + 3 * l], d_in[10 + 3 * l],
                                d_in[12 + 2 * l], d_in[13 + 2 * l], d_in[8 + l]);
        for (int hop = 0; hop < 3; hop++) {
            k_spmm_csr<<<SPG, 256>>>(hop & 1);
        }
        if (l == 0) {
            k_rating<<<1024, 256>>>(user, pos, neg);
            k_brilog<<<1024, 256>>>(s_bri, -1.f, 1);
            k_brilog<<<1024, 256>>>(i_bri, -1.f, 3);
        } else if (l == 1) {
            k_brilog<<<1024, 256>>>(s_bri, 1.f, 2);
            k_brilog<<<1024, 256>>>(i_bri, 1.f, 4);
        } else if (l == 2) {
            k_gsoc<<<128, 256>>>();
        } else {
            k_gmean<<<1024, 256>>>(i_bri, 0, 72);
            k_gmean<<<1024, 256>>>(i_bri_pos, NU_, 136);
        }
    }
    k_final<<<1, 1>>>((float*)d_out);
}

// round 8
// speedup vs baseline: 2.1905x; 1.0975x over previous
#include <cuda_runtime.h>
#include <cuda_bf16.h>
#include <math.h>

#define NU_  100000
#define NI_  50000
#define NT_  150000
#define NT4_ 600000          // 4 layers concatenated
#define D_   64
#define NNZ_ 2400000
#define NNZ4_ 9600000
#define BRI_ 50000
#define SCB4_ 586            // ceil(600000/1024)

// Per-layer regions concatenated: layer l occupies rows [l*NT_, (l+1)*NT_).
__device__ __nv_bfloat16 g_Xh[(size_t)NT4_ * D_];
__device__ __nv_bfloat16 g_Yh[(size_t)NT4_ * D_];
__device__ float g_acc[(size_t)NT4_ * D_];
// Unified CSR across 4 adjacencies (global scan => layer l edges at [l*NNZ_,...))
__device__ int  g_rowptr[NT4_ + 1];
__device__ int  g_cnt[NT4_];
__device__ int  g_pos[NT4_];
__device__ int2 g_edges[NNZ4_];  // (local col, float_bits(val))
__device__ int  g_bsum[SCB4_];
__device__ int  g_boff[SCB4_];
// Scalar accumulators + ordering flag
__device__ float g_scal[256];
__device__ int g_ordB;

struct Ptrs { const void* p[26]; };

__device__ __forceinline__ float sp_(float x) {  // softplus
    return (x > 15.f) ? x : log1pf(expf(x));
}

// ---------------------------------------------------------------------------
// Zero scalar accumulators + detect input ordering by inspecting d_in[8]:
// int32 node ids < 150000 have bit patterns < 0x04000000; uniform floats don't.
__global__ void k_setup(const unsigned* __restrict__ p8) {
    int t = threadIdx.x;
    if (t < 256) g_scal[t] = 0.f;
    if (t == 0) {
        int fl = 0;
        for (int i = 0; i < 64; i++)
            if (p8[i] > 0x04000000u) fl++;
        g_ordB = (fl > 32) ? 1 : 0;
    }
}

// Batched: X(bf16) = acc(fp32) = concat(user_emb, item_emb) for all 4 layers;
// zero the 600K-row histogram.
__global__ void __launch_bounds__(256) k_init(Ptrs P) {
    const int PL = NT_ * D_ / 8;  // 1.2M chunks per layer
    int i = blockIdx.x * 256 + threadIdx.x;
    if (i >= 4 * PL) return;
    if (i < NT4_) g_cnt[i] = 0;
    int l = i / PL;
    int f = (i - l * PL) * 8;
    const float* eu = (const float*)P.p[2 * l];
    const float* ei = (const float*)P.p[2 * l + 1];
    const float* src = (f < NU_ * D_) ? (eu + f) : (ei + (f - NU_ * D_));
    float4 a = *(const float4*)(src);
    float4 b = *(const float4*)(src + 4);
    size_t o = (size_t)l * NT_ * D_ + f;
    *(float4*)(g_acc + o)     = a;
    *(float4*)(g_acc + o + 4) = b;
    __nv_bfloat162 h[4];
    h[0] = __float22bfloat162_rn(make_float2(a.x, a.y));
    h[1] = __float22bfloat162_rn(make_float2(a.z, a.w));
    h[2] = __float22bfloat162_rn(make_float2(b.x, b.y));
    h[3] = __float22bfloat162_rn(make_float2(b.z, b.w));
    *(uint4*)(g_Xh + o) = *(uint4*)h;
}

// Batched histogram over all 4 adjacencies.
__global__ void __launch_bounds__(256) k_hist(Ptrs P) {
    int e = blockIdx.x * 256 + threadIdx.x;
    if (e >= NNZ4_) return;
    int l = e / NNZ_;
    int el = e - l * NNZ_;
    const int* rows = g_ordB ? (const int*)P.p[12 + 2 * l]
                             : (const int*)P.p[8 + 3 * l];
    atomicAdd(&g_cnt[l * NT_ + rows[el]], 1);
}

// Multi-block scan over 600K counts, phase A: per-block sums.
__global__ void __launch_bounds__(1024) k_scanA() {
    __shared__ int sm[1024];
    int t = threadIdx.x;
    int i = blockIdx.x * 1024 + t;
    sm[t] = (i < NT4_) ? g_cnt[i] : 0;
    __syncthreads();
    for (int s = 512; s; s >>= 1) {
        if (t < s) sm[t] += sm[t + s];
        __syncthreads();
    }
    if (t == 0) g_bsum[blockIdx.x] = sm[0];
}

// Phase B: single block scans the 586 block sums (exclusive).
__global__ void __launch_bounds__(1024) k_scanB() {
    __shared__ int sm[1024];
    int t = threadIdx.x;
    int v = (t < SCB4_) ? g_bsum[t] : 0;
    sm[t] = v;
    __syncthreads();
    for (int o = 1; o < 1024; o <<= 1) {
        int u = (t >= o) ? sm[t - o] : 0;
        __syncthreads();
        sm[t] += u;
        __syncthreads();
    }
    if (t < SCB4_) g_boff[t] = sm[t] - v;
}

// Phase C: per-block local scan + global offset -> rowptr, pos.
__global__ void __launch_bounds__(1024) k_scanC() {
    __shared__ int sm[1024];
    int t = threadIdx.x;
    int i = blockIdx.x * 1024 + t;
    int v = (i < NT4_) ? g_cnt[i] : 0;
    sm[t] = v;
    __syncthreads();
    for (int o = 1; o < 1024; o <<= 1) {
        int u = (t >= o) ? sm[t - o] : 0;
        __syncthreads();
        sm[t] += u;
        __syncthreads();
    }
    int excl = g_boff[blockIdx.x] + sm[t] - v;
    if (i < NT4_) {
        g_rowptr[i] = excl;
        g_pos[i] = excl;
    }
    if (i == NT4_ - 1) g_rowptr[NT4_] = excl + v;
}

// Batched scatter (fp-sum order nondeterminism ~1e-7, tol 1e-3).
__global__ void __launch_bounds__(256) k_scatter(Ptrs P) {
    int e = blockIdx.x * 256 + threadIdx.x;
    if (e >= NNZ4_) return;
    int l = e / NNZ_;
    int el = e - l * NNZ_;
    const int *rows, *cols;
    const float* vals;
    if (g_ordB) {
        rows = (const int*)P.p[12 + 2 * l];
        cols = (const int*)P.p[13 + 2 * l];
        vals = (const float*)P.p[8 + l];
    } else {
        rows = (const int*)P.p[8 + 3 * l];
        cols = (const int*)P.p[9 + 3 * l];
        vals = (const float*)P.p[10 + 3 * l];
    }
    int r = rows[el];
    int c = cols[el];
    float v = vals[el];
    int p = atomicAdd(&g_pos[l * NT_ + r], 1);
    g_edges[p] = make_int2(c, __float_as_int(v));
}

// Batched CSR SpMM over all 4 layers + fused residual/acc epilogue.
// 8 threads per row; edges loaded uniformly per group (L1 broadcast, no shfl).
__global__ void __launch_bounds__(256) k_spmm_csr(int dir) {
    int tid = blockIdx.x * 256 + threadIdx.x;
    int row = tid >> 3;                 // global row in [0, NT4_)
    if (row >= NT4_) return;
    int k = tid & 7;
    int l = row / NT_;
    const __nv_bfloat16* xb = (dir ? g_Yh : g_Xh) + (size_t)l * NT_ * D_;
    __nv_bfloat16* y = dir ? g_Xh : g_Yh;
    int s0 = g_rowptr[row];
    int s1 = g_rowptr[row + 1];
    float s[8] = {0.f, 0.f, 0.f, 0.f, 0.f, 0.f, 0.f, 0.f};
#pragma unroll 4
    for (int e = s0; e < s1; e++) {
        int2 ed = g_edges[e];           // uniform in 8-lane group -> broadcast
        float vj = __int_as_float(ed.y);
        uint4 raw = *(const uint4*)(xb + ed.x * D_ + k * 8);
        const __nv_bfloat162* p = (const __nv_bfloat162*)&raw;
#pragma unroll
        for (int q = 0; q < 4; q++) {
            float2 f = __bfloat1622float2(p[q]);
            s[q * 2]     += vj * f.x;
            s[q * 2 + 1] += vj * f.y;
        }
    }
    size_t ro = (size_t)row * D_ + k * 8;
    // residual: + h[row]
    {
        uint4 raw = *(const uint4*)((dir ? g_Yh : g_Xh) + ro);
        const __nv_bfloat162* p = (const __nv_bfloat162*)&raw;
#pragma unroll
        for (int q = 0; q < 4; q++) {
            float2 f = __bfloat1622float2(p[q]);
            s[q * 2]     += f.x;
            s[q * 2 + 1] += f.y;
        }
    }
    // store y (bf16)
    {
        __nv_bfloat162 h[4];
#pragma unroll
        for (int q = 0; q < 4; q++)
            h[q] = __float22bfloat162_rn(make_float2(s[q * 2], s[q * 2 + 1]));
        *(uint4*)(y + ro) = *(uint4*)h;
    }
    // acc += s (fp32)
    {
        float4* ap = (float4*)(g_acc + ro);
        float4 a0 = ap[0], a1 = ap[1];
        a0.x += s[0]; a0.y += s[1]; a0.z += s[2]; a0.w += s[3];
        a1.x += s[4]; a1.y += s[5]; a1.z += s[6]; a1.w += s[7];
        ap[0] = a0; ap[1] = a1;
    }
}

// ---------------------------------------------------------------------------
// Loss kernels (read g_acc at a layer row-offset, 0.25 mean factor inline).

__global__ void __launch_bounds__(256) k_rating(const int* __restrict__ user,
                                                const int* __restrict__ pos,
                                                const int* __restrict__ neg) {
    int gt = blockIdx.x * 256 + threadIdx.x;
    int w = gt >> 5, lane = gt & 31;
    if (w >= 8192) return;
    int ur = user[w] * D_;                 // layer 0
    int pr = (NU_ + pos[w]) * D_;
    int nr = (NU_ + neg[w]) * D_;
    float pp = 0.f, np = 0.f, l2 = 0.f;
#pragma unroll
    for (int q = 0; q < 2; q++) {
        int d = lane * 2 + q;
        float u = 0.25f * g_acc[ur + d];
        float a = 0.25f * g_acc[pr + d];
        float b = 0.25f * g_acc[nr + d];
        pp += u * a;
        np += u * b;
        l2 += u * u + a * a + b * b;
    }
    for (int o = 16; o; o >>= 1) {
        pp += __shfl_down_sync(0xffffffffu, pp, o);
        np += __shfl_down_sync(0xffffffffu, np, o);
        l2 += __shfl_down_sync(0xffffffffu, l2, o);
    }
    if (lane == 0) atomicAdd(&g_scal[0], sp_(np - pp) + 0.01f * l2);
}

__global__ void __launch_bounds__(256) k_brilog(const int* __restrict__ idx,
                                                int rowoff, float sign, int slot) {
    int t = blockIdx.x * 256 + threadIdx.x;  // exactly 4096*64 threads
    int i = t >> 6, d = t & 63;
    float x = 0.25f * g_acc[(size_t)(rowoff + idx[i]) * D_ + d];
    float val = -sp_(sign * x);
    __shared__ float sm[256];
    sm[threadIdx.x] = val;
    __syncthreads();
    for (int s = 128; s; s >>= 1) {
        if (threadIdx.x < s) sm[threadIdx.x] += sm[threadIdx.x + s];
        __syncthreads();
    }
    if (threadIdx.x == 0) atomicAdd(&g_scal[slot], sm[0]);
}

__global__ void __launch_bounds__(256) k_gsoc() {
    int gt = blockIdx.x * 256 + threadIdx.x;  // grid = 128 blocks -> 512 row groups
    int d = gt & 63;
    int rg = gt >> 6;
    const size_t base = (size_t)2 * NT_ * D_;  // layer 2
    float s = 0.f;
    for (int r = BRI_ + rg; r < BRI_ + 50000; r += 512)
        s += g_acc[base + (size_t)r * D_ + d];
    __shared__ float sm[256];
    sm[threadIdx.x] = s;
    __syncthreads();
    if (threadIdx.x < 64)
        atomicAdd(&g_scal[8 + threadIdx.x],
                  sm[threadIdx.x] + sm[threadIdx.x + 64] +
                  sm[threadIdx.x + 128] + sm[threadIdx.x + 192]);
}

__global__ void __launch_bounds__(256) k_gmean(const int* __restrict__ idx,
                                               int rowoff, int slot) {
    int t = blockIdx.x * 256 + threadIdx.x;  // exactly 4096*64 threads
    int i = t >> 6, d = t & 63;
    float x = 0.25f * g_acc[(size_t)(rowoff + idx[i]) * D_ + d];
    float sg = 1.f / (1.f + expf(-x));
    __shared__ float sm[256];
    sm[threadIdx.x] = sg;
    __syncthreads();
    if (threadIdx.x < 64)
        atomicAdd(&g_scal[slot + threadIdx.x],
                  sm[threadIdx.x] + sm[threadIdx.x + 64] +
                  sm[threadIdx.x + 128] + sm[threadIdx.x + 192]);
}

__global__ void k_final(float* __restrict__ out) {
    double sgr = 0.0, sgf = 0.0, sir = 0.0, sif = 0.0;
    for (int d = 0; d < 64; d++) {
        double gs = 0.25 * (double)g_scal[8 + d] / 50000.0;
        double sg = 1.0 / (1.0 + exp(-gs));
        sgr += log(sg);
        sgf += log(1.0 - sg);
    }
    for (int d = 0; d < 128; d++) {
        double g = (double)g_scal[72 + d] / 4096.0;
        sir += log(g);
        sif += log1p(-g);
    }
    double A1 = g_scal[0], A2 = g_scal[1], A3 = g_scal[2];
    double A5 = g_scal[3], A6 = g_scal[4];
    double social = -(A2 / (4096.0 * 128.0) + sgr / 128.0)
                    - (A3 / (4096.0 * 128.0) + sgf / 128.0);
    double infor  = -(A5 / (4096.0 * 192.0) + sir / 192.0)
                    - (A6 / (4096.0 * 192.0) + sif / 192.0);
    double rating = A1;
    double obj = rating + 100.0 * social + 1000.0 * infor;
    out[0] = (float)obj;
    out[1] = (float)rating;
    out[2] = (float)social;
    out[3] = (float)infor;
}

extern "C" void kernel_launch(void* const* d_in, const int* in_sizes, int n_in,
                              void* d_out, int out_size) {
    Ptrs P;
    for (int i = 0; i < 26; i++) P.p[i] = d_in[i];
    const int* user      = (const int*)d_in[20];
    const int* pos       = (const int*)d_in[21];
    const int* neg       = (const int*)d_in[22];
    const int* s_bri     = (const int*)d_in[23];
    const int* i_bri     = (const int*)d_in[24];
    const int* i_bri_pos = (const int*)d_in[25];

    k_setup<<<1, 256>>>((const unsigned*)d_in[8]);

    const int CHG4 = (NT4_ * D_ / 8 + 255) / 256;  // 18750
    const int EDG4 = (NNZ4_ + 255) / 256;          // 37500
    const int SPG4 = (NT4_ * 8 + 255) / 256;       // 18750

    k_init<<<CHG4, 256>>>(P);
    k_hist<<<EDG4, 256>>>(P);
    k_scanA<<<SCB4_, 1024>>>();
    k_scanB<<<1, 1024>>>();
    k_scanC<<<SCB4_, 1024>>>();
    k_scatter<<<EDG4, 256>>>(P);
    for (int hop = 0; hop < 3; hop++)
        k_spmm_csr<<<SPG4, 256>>>(hop & 1);

    k_rating<<<1024, 256>>>(user, pos, neg);
    k_brilog<<<1024, 256>>>(s_bri, 0, -1.f, 1);            // layer 0
    k_brilog<<<1024, 256>>>(i_bri, 0, -1.f, 3);            // layer 0
    k_brilog<<<1024, 256>>>(s_bri, NT_, 1.f, 2);           // layer 1
    k_brilog<<<1024, 256>>>(i_bri, NT_, 1.f, 4);           // layer 1
    k_gsoc<<<128, 256>>>();                                // layer 2
    k_gmean<<<1024, 256>>>(i_bri, 3 * NT_, 72);            // layer 3 users
    k_gmean<<<1024, 256>>>(i_bri_pos, 3 * NT_ + NU_, 136); // layer 3 items
    k_final<<<1, 1>>>((float*)d_out);
}

// round 9
// speedup vs baseline: 2.3197x; 1.0590x over previous
#include <cuda_runtime.h>
#include <cuda_bf16.h>
#include <math.h>

#define NU_  100000
#define NI_  50000
#define NT_  150000
#define NT4_ 600000          // 4 layers concatenated
#define D_   64
#define NNZ_ 2400000
#define NNZ4_ 9600000
#define BRI_ 50000
#define SCB4_ 586            // ceil(600000/1024)

// Hop buffers (bf16). Layer l occupies rows [l*NT_, (l+1)*NT_).
// h0 = g_Xh (initial embeddings), h1 = g_B1, h2 = g_B2, h3 = g_B3.
__device__ __nv_bfloat16 g_Xh[(size_t)NT4_ * D_];
__device__ __nv_bfloat16 g_B1[(size_t)NT4_ * D_];
__device__ __nv_bfloat16 g_B2[(size_t)NT4_ * D_];
__device__ __nv_bfloat16 g_B3[(size_t)NT4_ * D_];
// Unified CSR across 4 adjacencies
__device__ int  g_rowptr[NT4_ + 1];
__device__ int  g_cnt[NT4_];
__device__ int  g_pos[NT4_];
__device__ int2 g_edges[NNZ4_];  // (local col, float_bits(val))
__device__ int  g_bsum[SCB4_];
__device__ int  g_boff[SCB4_];
// Scalar accumulators + ordering flag
__device__ float g_scal[256];
__device__ int g_ordB;

struct Ptrs { const void* p[26]; };

__device__ __forceinline__ float sp_(float x) {  // softplus
    return (x > 15.f) ? x : log1pf(expf(x));
}

// acc(row) = 0.25*(h0 + h1 + h2 + h3); h0 from the fp32 input embedding,
// h1..h3 from the bf16 hop buffers at global row grow.
__device__ __forceinline__ float acc4_(const float* __restrict__ emb,
                                       size_t elocal, size_t grow, int d) {
    float h0 = emb[elocal * D_ + d];
    size_t o = grow * D_ + d;
    float h1 = __bfloat162float(g_B1[o]);
    float h2 = __bfloat162float(g_B2[o]);
    float h3 = __bfloat162float(g_B3[o]);
    return 0.25f * (h0 + h1 + h2 + h3);
}

// ---------------------------------------------------------------------------
// Zero scalar accumulators + detect input ordering by inspecting d_in[8]:
// int32 node ids < 150000 have bit patterns < 0x04000000; uniform floats don't.
__global__ void k_setup(const unsigned* __restrict__ p8) {
    int t = threadIdx.x;
    if (t < 256) g_scal[t] = 0.f;
    if (t == 0) {
        int fl = 0;
        for (int i = 0; i < 64; i++)
            if (p8[i] > 0x04000000u) fl++;
        g_ordB = (fl > 32) ? 1 : 0;
    }
}

// Batched: Xh(bf16) = concat(user_emb, item_emb) for all 4 layers; zero hist.
__global__ void __launch_bounds__(256) k_init(Ptrs P) {
    const int PL = NT_ * D_ / 8;  // 1.2M chunks per layer
    int i = blockIdx.x * 256 + threadIdx.x;
    if (i >= 4 * PL) return;
    if (i < NT4_) g_cnt[i] = 0;
    int l = i / PL;
    int f = (i - l * PL) * 8;
    const float* eu = (const float*)P.p[2 * l];
    const float* ei = (const float*)P.p[2 * l + 1];
    const float* src = (f < NU_ * D_) ? (eu + f) : (ei + (f - NU_ * D_));
    float4 a = *(const float4*)(src);
    float4 b = *(const float4*)(src + 4);
    __nv_bfloat162 h[4];
    h[0] = __float22bfloat162_rn(make_float2(a.x, a.y));
    h[1] = __float22bfloat162_rn(make_float2(a.z, a.w));
    h[2] = __float22bfloat162_rn(make_float2(b.x, b.y));
    h[3] = __float22bfloat162_rn(make_float2(b.z, b.w));
    *(uint4*)(g_Xh + (size_t)l * NT_ * D_ + f) = *(uint4*)h;
}

// Batched histogram over all 4 adjacencies.
__global__ void __launch_bounds__(256) k_hist(Ptrs P) {
    int e = blockIdx.x * 256 + threadIdx.x;
    if (e >= NNZ4_) return;
    int l = e / NNZ_;
    int el = e - l * NNZ_;
    const int* rows = g_ordB ? (const int*)P.p[12 + 2 * l]
                             : (const int*)P.p[8 + 3 * l];
    atomicAdd(&g_cnt[l * NT_ + rows[el]], 1);
}

// Multi-block scan over 600K counts, phase A: per-block sums.
__global__ void __launch_bounds__(1024) k_scanA() {
    __shared__ int sm[1024];
    int t = threadIdx.x;
    int i = blockIdx.x * 1024 + t;
    sm[t] = (i < NT4_) ? g_cnt[i] : 0;
    __syncthreads();
    for (int s = 512; s; s >>= 1) {
        if (t < s) sm[t] += sm[t + s];
        __syncthreads();
    }
    if (t == 0) g_bsum[blockIdx.x] = sm[0];
}

// Phase B: single block scans the 586 block sums (exclusive).
__global__ void __launch_bounds__(1024) k_scanB() {
    __shared__ int sm[1024];
    int t = threadIdx.x;
    int v = (t < SCB4_) ? g_bsum[t] : 0;
    sm[t] = v;
    __syncthreads();
    for (int o = 1; o < 1024; o <<= 1) {
        int u = (t >= o) ? sm[t - o] : 0;
        __syncthreads();
        sm[t] += u;
        __syncthreads();
    }
    if (t < SCB4_) g_boff[t] = sm[t] - v;
}

// Phase C: per-block local scan + global offset -> rowptr, pos.
__global__ void __launch_bounds__(1024) k_scanC() {
    __shared__ int sm[1024];
    int t = threadIdx.x;
    int i = blockIdx.x * 1024 + t;
    int v = (i < NT4_) ? g_cnt[i] : 0;
    sm[t] = v;
    __syncthreads();
    for (int o = 1; o < 1024; o <<= 1) {
        int u = (t >= o) ? sm[t - o] : 0;
        __syncthreads();
        sm[t] += u;
        __syncthreads();
    }
    int excl = g_boff[blockIdx.x] + sm[t] - v;
    if (i < NT4_) {
        g_rowptr[i] = excl;
        g_pos[i] = excl;
    }
    if (i == NT4_ - 1) g_rowptr[NT4_] = excl + v;
}

// Batched scatter (fp-sum order nondeterminism ~1e-7, tol 1e-3).
__global__ void __launch_bounds__(256) k_scatter(Ptrs P) {
    int e = blockIdx.x * 256 + threadIdx.x;
    if (e >= NNZ4_) return;
    int l = e / NNZ_;
    int el = e - l * NNZ_;
    const int *rows, *cols;
    const float* vals;
    if (g_ordB) {
        rows = (const int*)P.p[12 + 2 * l];
        cols = (const int*)P.p[13 + 2 * l];
        vals = (const float*)P.p[8 + l];
    } else {
        rows = (const int*)P.p[8 + 3 * l];
        cols = (const int*)P.p[9 + 3 * l];
        vals = (const float*)P.p[10 + 3 * l];
    }
    int r = rows[el];
    int c = cols[el];
    float v = vals[el];
    int p = atomicAdd(&g_pos[l * NT_ + r], 1);
    g_edges[p] = make_int2(c, __float_as_int(v));
}

// Batched CSR SpMM + residual; writes the hop's own bf16 buffer.
// 8 threads per row; edges loaded uniformly per group (L1 broadcast).
__global__ void __launch_bounds__(256) k_spmm_csr(int hop) {
    int tid = blockIdx.x * 256 + threadIdx.x;
    int row = tid >> 3;                 // global row in [0, NT4_)
    if (row >= NT4_) return;
    int k = tid & 7;
    const __nv_bfloat16* xg = (hop == 0) ? g_Xh : ((hop == 1) ? g_B1 : g_B2);
    __nv_bfloat16* y = (hop == 0) ? g_B1 : ((hop == 1) ? g_B2 : g_B3);
    int l = row / NT_;
    const __nv_bfloat16* xb = xg + (size_t)l * NT_ * D_;
    int s0 = g_rowptr[row];
    int s1 = g_rowptr[row + 1];
    float s[8] = {0.f, 0.f, 0.f, 0.f, 0.f, 0.f, 0.f, 0.f};
#pragma unroll 4
    for (int e = s0; e < s1; e++) {
        int2 ed = g_edges[e];           // uniform in 8-lane group -> broadcast
        float vj = __int_as_float(ed.y);
        uint4 raw = *(const uint4*)(xb + ed.x * D_ + k * 8);
        const __nv_bfloat162* p = (const __nv_bfloat162*)&raw;
#pragma unroll
        for (int q = 0; q < 4; q++) {
            float2 f = __bfloat1622float2(p[q]);
            s[q * 2]     += vj * f.x;
            s[q * 2 + 1] += vj * f.y;
        }
    }
    size_t ro = (size_t)row * D_ + k * 8;
    // residual: + h[row]
    {
        uint4 raw = *(const uint4*)(xg + ro);
        const __nv_bfloat162* p = (const __nv_bfloat162*)&raw;
#pragma unroll
        for (int q = 0; q < 4; q++) {
            float2 f = __bfloat1622float2(p[q]);
            s[q * 2]     += f.x;
            s[q * 2 + 1] += f.y;
        }
    }
    // store y (bf16)
    __nv_bfloat162 h[4];
#pragma unroll
    for (int q = 0; q < 4; q++)
        h[q] = __float22bfloat162_rn(make_float2(s[q * 2], s[q * 2 + 1]));
    *(uint4*)(y + ro) = *(uint4*)h;
}

// ---------------------------------------------------------------------------
// Loss kernels: reconstruct 0.25*(h0+h1+h2+h3) on the fly.

__global__ void __launch_bounds__(256) k_rating(const int* __restrict__ user,
                                                const int* __restrict__ pos,
                                                const int* __restrict__ neg,
                                                const float* __restrict__ ue,
                                                const float* __restrict__ ie) {
    int gt = blockIdx.x * 256 + threadIdx.x;
    int w = gt >> 5, lane = gt & 31;
    if (w >= 8192) return;
    int ur = user[w];
    int pr = pos[w];
    int nr = neg[w];
    float pp = 0.f, np = 0.f, l2 = 0.f;
#pragma unroll
    for (int q = 0; q < 2; q++) {
        int d = lane * 2 + q;
        float u = acc4_(ue, ur, ur, d);                  // layer 0, user
        float a = acc4_(ie, pr, (size_t)NU_ + pr, d);    // layer 0, item
        float b = acc4_(ie, nr, (size_t)NU_ + nr, d);
        pp += u * a;
        np += u * b;
        l2 += u * u + a * a + b * b;
    }
    for (int o = 16; o; o >>= 1) {
        pp += __shfl_down_sync(0xffffffffu, pp, o);
        np += __shfl_down_sync(0xffffffffu, np, o);
        l2 += __shfl_down_sync(0xffffffffu, l2, o);
    }
    if (lane == 0) atomicAdd(&g_scal[0], sp_(np - pp) + 0.01f * l2);
}

// Sum of -softplus(sign*acc) over 4096 gathered user rows of layer at rowoff.
__global__ void __launch_bounds__(256) k_brilog(const int* __restrict__ idx,
                                                const float* __restrict__ emb,
                                                int rowoff, float sign, int slot) {
    int t = blockIdx.x * 256 + threadIdx.x;  // exactly 4096*64 threads
    int i = t >> 6, d = t & 63;
    int r = idx[i];
    float x = acc4_(emb, r, (size_t)rowoff + r, d);
    float val = -sp_(sign * x);
    __shared__ float sm[256];
    sm[threadIdx.x] = val;
    __syncthreads();
    for (int s = 128; s; s >>= 1) {
        if (threadIdx.x < s) sm[threadIdx.x] += sm[threadIdx.x + s];
        __syncthreads();
    }
    if (threadIdx.x == 0) atomicAdd(&g_scal[slot], sm[0]);
}

// Column sums of acc over layer-2 user rows [BRI_, BRI_+50000) -> g_scal[8+d].
__global__ void __launch_bounds__(256) k_gsoc(const float* __restrict__ sgu) {
    int gt = blockIdx.x * 256 + threadIdx.x;  // 128 blocks -> 512 row groups
    int d = gt & 63;
    int rg = gt >> 6;
    const size_t base = (size_t)2 * NT_;  // layer 2 global row offset
    float s = 0.f;
    for (int r = BRI_ + rg; r < BRI_ + 50000; r += 512)
        s += acc4_(sgu, r, base + r, d);
    __shared__ float sm[256];
    sm[threadIdx.x] = s;
    __syncthreads();
    if (threadIdx.x < 64)
        atomicAdd(&g_scal[8 + threadIdx.x],
                  sm[threadIdx.x] + sm[threadIdx.x + 64] +
                  sm[threadIdx.x + 128] + sm[threadIdx.x + 192]);
}

// Column sums of sigmoid(acc) over 4096 gathered rows -> g_scal[slot+d].
// emb indexed by idx directly; grow = growoff + idx.
__global__ void __launch_bounds__(256) k_gmean(const int* __restrict__ idx,
                                               const float* __restrict__ emb,
                                               int growoff, int slot) {
    int t = blockIdx.x * 256 + threadIdx.x;  // exactly 4096*64 threads
    int i = t >> 6, d = t & 63;
    int r = idx[i];
    float x = acc4_(emb, r, (size_t)growoff + r, d);
    float sg = 1.f / (1.f + expf(-x));
    __shared__ float sm[256];
    sm[threadIdx.x] = sg;
    __syncthreads();
    if (threadIdx.x < 64)
        atomicAdd(&g_scal[slot + threadIdx.x],
                  sm[threadIdx.x] + sm[threadIdx.x + 64] +
                  sm[threadIdx.x + 128] + sm[threadIdx.x + 192]);
}

__global__ void k_final(float* __restrict__ out) {
    double sgr = 0.0, sgf = 0.0, sir = 0.0, sif = 0.0;
    for (int d = 0; d < 64; d++) {
        double gs = (double)g_scal[8 + d] / 50000.0;
        double sg = 1.0 / (1.0 + exp(-gs));
        sgr += log(sg);
        sgf += log(1.0 - sg);
    }
    for (int d = 0; d < 128; d++) {
        double g = (double)g_scal[72 + d] / 4096.0;
        sir += log(g);
        sif += log1p(-g);
    }
    double A1 = g_scal[0], A2 = g_scal[1], A3 = g_scal[2];
    double A5 = g_scal[3], A6 = g_scal[4];
    double social = -(A2 / (4096.0 * 128.0) + sgr / 128.0)
                    - (A3 / (4096.0 * 128.0) + sgf / 128.0);
    double infor  = -(A5 / (4096.0 * 192.0) + sir / 192.0)
                    - (A6 / (4096.0 * 192.0) + sif / 192.0);
    double rating = A1;
    double obj = rating + 100.0 * social + 1000.0 * infor;
    out[0] = (float)obj;
    out[1] = (float)rating;
    out[2] = (float)social;
    out[3] = (float)infor;
}

extern "C" void kernel_launch(void* const* d_in, const int* in_sizes, int n_in,
                              void* d_out, int out_size) {
    Ptrs P;
    for (int i = 0; i < 26; i++) P.p[i] = d_in[i];
    const float* ue  = (const float*)d_in[0];
    const float* ie  = (const float*)d_in[1];
    const float* fue = (const float*)d_in[2];
    const float* sgu = (const float*)d_in[4];
    const float* igu = (const float*)d_in[6];
    const float* igi = (const float*)d_in[7];
    const int* user      = (const int*)d_in[20];
    const int* pos       = (const int*)d_in[21];
    const int* neg       = (const int*)d_in[22];
    const int* s_bri     = (const int*)d_in[23];
    const int* i_bri     = (const int*)d_in[24];
    const int* i_bri_pos = (const int*)d_in[25];

    k_setup<<<1, 256>>>((const unsigned*)d_in[8]);

    const int CHG4 = (NT4_ * D_ / 8 + 255) / 256;  // 18750
    const int EDG4 = (NNZ4_ + 255) / 256;          // 37500
    const int SPG4 = (NT4_ * 8 + 255) / 256;       // 18750

    k_init<<<CHG4, 256>>>(P);
    k_hist<<<EDG4, 256>>>(P);
    k_scanA<<<SCB4_, 1024>>>();
    k_scanB<<<1, 1024>>>();
    k_scanC<<<SCB4_, 1024>>>();
    k_scatter<<<EDG4, 256>>>(P);
    for (int hop = 0; hop < 3; hop++)
        k_spmm_csr<<<SPG4, 256>>>(hop);

    k_rating<<<1024, 256>>>(user, pos, neg, ue, ie);
    k_brilog<<<1024, 256>>>(s_bri, ue, 0, -1.f, 1);               // layer 0
    k_brilog<<<1024, 256>>>(i_bri, ue, 0, -1.f, 3);               // layer 0
    k_brilog<<<1024, 256>>>(s_bri, fue, NT_, 1.f, 2);             // layer 1
    k_brilog<<<1024, 256>>>(i_bri, fue, NT_, 1.f, 4);             // layer 1
    k_gsoc<<<128, 256>>>(sgu);                                    // layer 2
    k_gmean<<<1024, 256>>>(i_bri, igu, 3 * NT_, 72);              // layer 3 users
    k_gmean<<<1024, 256>>>(i_bri_pos, igi, 3 * NT_ + NU_, 136);   // layer 3 items
    k_final<<<1, 1>>>((float*)d_out);
}

// round 12
// speedup vs baseline: 2.3210x; 1.0006x over previous
#include <cuda_runtime.h>
#include <cuda_bf16.h>
#include <math.h>

#define NU_  100000
#define NI_  50000
#define NT_  150000
#define NT4_ 600000          // 4 layers concatenated
#define D_   64
#define NNZ_ 2400000
#define NNZ4_ 9600000
#define BRI_ 50000
#define SCB4_ 586            // ceil(600000/1024)

// Hop buffers (bf16). Layer l occupies rows [l*NT_, (l+1)*NT_).
// h0 = g_Xh (initial embeddings), h1 = g_B1, h2 = g_B2, h3 = g_B3.
__device__ __nv_bfloat16 g_Xh[(size_t)NT4_ * D_];
__device__ __nv_bfloat16 g_B1[(size_t)NT4_ * D_];
__device__ __nv_bfloat16 g_B2[(size_t)NT4_ * D_];
__device__ __nv_bfloat16 g_B3[(size_t)NT4_ * D_];
// Unified CSR across 4 adjacencies
__device__ int  g_rowptr[NT4_ + 1];
__device__ int  g_cnt[NT4_];
__device__ int  g_pos[NT4_];
__device__ int2 g_edges[NNZ4_];  // (local col, float_bits(val))
__device__ int  g_bsum[SCB4_];
__device__ int  g_boff[SCB4_];
// Which rows' hop-3 outputs are actually consumed by the losses.
__device__ unsigned char g_mask[NT4_];
// Scalar accumulators + ordering flag
__device__ float g_scal[256];
__device__ int g_ordB;

struct Ptrs { const void* p[26]; };

__device__ __forceinline__ float sp_(float x) {  // softplus
    return (x > 15.f) ? x : log1pf(expf(x));
}

// acc(row) = 0.25*(h0 + h1 + h2 + h3); h0 from the fp32 input embedding,
// h1..h3 from the bf16 hop buffers at global row grow.
__device__ __forceinline__ float acc4_(const float* __restrict__ emb,
                                       size_t elocal, size_t grow, int d) {
    float h0 = emb[elocal * D_ + d];
    size_t o = grow * D_ + d;
    float h1 = __bfloat162float(g_B1[o]);
    float h2 = __bfloat162float(g_B2[o]);
    float h3 = __bfloat162float(g_B3[o]);
    return 0.25f * (h0 + h1 + h2 + h3);
}

// ---------------------------------------------------------------------------
// Zero scalar accumulators + detect input ordering by inspecting d_in[8]:
// int32 node ids < 150000 have bit patterns < 0x04000000; uniform floats don't.
__global__ void k_setup(const unsigned* __restrict__ p8) {
    int t = threadIdx.x;
    if (t < 256) g_scal[t] = 0.f;
    if (t == 0) {
        int fl = 0;
        for (int i = 0; i < 64; i++)
            if (p8[i] > 0x04000000u) fl++;
        g_ordB = (fl > 32) ? 1 : 0;
    }
}

// Batched: Xh(bf16) = concat(user_emb, item_emb) for all 4 layers;
// zero histogram + mask.
__global__ void __launch_bounds__(256) k_init(Ptrs P) {
    const int PL = NT_ * D_ / 8;  // 1.2M chunks per layer
    int i = blockIdx.x * 256 + threadIdx.x;
    if (i >= 4 * PL) return;
    if (i < NT4_) { g_cnt[i] = 0; g_mask[i] = 0; }
    int l = i / PL;
    int f = (i - l * PL) * 8;
    const float* eu = (const float*)P.p[2 * l];
    const float* ei = (const float*)P.p[2 * l + 1];
    const float* src = (f < NU_ * D_) ? (eu + f) : (ei + (f - NU_ * D_));
    float4 a = *(const float4*)(src);
    float4 b = *(const float4*)(src + 4);
    __nv_bfloat162 h[4];
    h[0] = __float22bfloat162_rn(make_float2(a.x, a.y));
    h[1] = __float22bfloat162_rn(make_float2(a.z, a.w));
    h[2] = __float22bfloat162_rn(make_float2(b.x, b.y));
    h[3] = __float22bfloat162_rn(make_float2(b.z, b.w));
    *(uint4*)(g_Xh + (size_t)l * NT_ * D_ + f) = *(uint4*)h;
}

// Mark the rows whose final-hop output is consumed by a loss.
__global__ void __launch_bounds__(256) k_mark(const int* __restrict__ user,
                                             const int* __restrict__ pos,
                                             const int* __restrict__ neg,
                                             const int* __restrict__ s_bri,
                                             const int* __restrict__ i_bri,
                                             const int* __restrict__ i_bri_pos) {
    int t = blockIdx.x * 256 + threadIdx.x;
    int r = -1;
    if      (t < 8192)           r = user[t];                       // L0 user
    else if (t < 16384)          r = NU_ + pos[t - 8192];           // L0 item
    else if (t < 24576)          r = NU_ + neg[t - 16384];          // L0 item
    else if (t < 28672)          r = s_bri[t - 24576];              // L0
    else if (t < 32768)          r = i_bri[t - 28672];              // L0
    else if (t < 36864)          r = NT_ + s_bri[t - 32768];        // L1
    else if (t < 40960)          r = NT_ + i_bri[t - 36864];        // L1
    else if (t < 45056)          r = 3 * NT_ + i_bri[t - 40960];    // L3 user
    else if (t < 49152)          r = 3 * NT_ + NU_ + i_bri_pos[t - 45056]; // L3 item
    else if (t < 99152)          r = 2 * NT_ + BRI_ + (t - 49152);  // L2 range
    if (r >= 0) g_mask[r] = 1;
}

// Batched histogram over all 4 adjacencies.
__global__ void __launch_bounds__(256) k_hist(Ptrs P) {
    int e = blockIdx.x * 256 + threadIdx.x;
    if (e >= NNZ4_) return;
    int l = e / NNZ_;
    int el = e - l * NNZ_;
    const int* rows = g_ordB ? (const int*)P.p[12 + 2 * l]
                             : (const int*)P.p[8 + 3 * l];
    atomicAdd(&g_cnt[l * NT_ + __ldcs(rows + el)], 1);
}

// Multi-block scan over 600K counts, phase A: per-block sums.
__global__ void __launch_bounds__(1024) k_scanA() {
    __shared__ int sm[1024];
    int t = threadIdx.x;
    int i = blockIdx.x * 1024 + t;
    sm[t] = (i < NT4_) ? g_cnt[i] : 0;
    __syncthreads();
    for (int s = 512; s; s >>= 1) {
        if (t < s) sm[t] += sm[t + s];
        __syncthreads();
    }
    if (t == 0) g_bsum[blockIdx.x] = sm[0];
}

// Phase B: single block scans the 586 block sums (exclusive).
__global__ void __launch_bounds__(1024) k_scanB() {
    __shared__ int sm[1024];
    int t = threadIdx.x;
    int v = (t < SCB4_) ? g_bsum[t] : 0;
    sm[t] = v;
    __syncthreads();
    for (int o = 1; o < 1024; o <<= 1) {
        int u = (t >= o) ? sm[t - o] : 0;
        __syncthreads();
        sm[t] += u;
        __syncthreads();
    }
    if (t < SCB4_) g_boff[t] = sm[t] - v;
}

// Phase C: per-block local scan + global offset -> rowptr, pos.
__global__ void __launch_bounds__(1024) k_scanC() {
    __shared__ int sm[1024];
    int t = threadIdx.x;
    int i = blockIdx.x * 1024 + t;
    int v = (i < NT4_) ? g_cnt[i] : 0;
    sm[t] = v;
    __syncthreads();
    for (int o = 1; o < 1024; o <<= 1) {
        int u = (t >= o) ? sm[t - o] : 0;
        __syncthreads();
        sm[t] += u;
        __syncthreads();
    }
    int excl = g_boff[blockIdx.x] + sm[t] - v;
    if (i < NT4_) {
        g_rowptr[i] = excl;
        g_pos[i] = excl;
    }
    if (i == NT4_ - 1) g_rowptr[NT4_] = excl + v;
}

// Batched scatter (fp-sum order nondeterminism ~1e-7, tol 1e-3).
__global__ void __launch_bounds__(256) k_scatter(Ptrs P) {
    int e = blockIdx.x * 256 + threadIdx.x;
    if (e >= NNZ4_) return;
    int l = e / NNZ_;
    int el = e - l * NNZ_;
    const int *rows, *cols;
    const float* vals;
    if (g_ordB) {
        rows = (const int*)P.p[12 + 2 * l];
        cols = (const int*)P.p[13 + 2 * l];
        vals = (const float*)P.p[8 + l];
    } else {
        rows = (const int*)P.p[8 + 3 * l];
        cols = (const int*)P.p[9 + 3 * l];
        vals = (const float*)P.p[10 + 3 * l];
    }
    int r = __ldcs(rows + el);
    int c = __ldcs(cols + el);
    float v = __ldcs(vals + el);
    int p = atomicAdd(&g_pos[l * NT_ + r], 1);
    g_edges[p] = make_int2(c, __float_as_int(v));
}

// Batched CSR SpMM + residual; writes the hop's own bf16 buffer.
// 8 threads per row; edges loaded uniformly per group (L1 broadcast),
// streamed with __ldcs so they don't evict the x working set from L2.
// On the final hop, rows nobody reads are skipped via g_mask.
__global__ void __launch_bounds__(256) k_spmm_csr(int hop) {
    int tid = blockIdx.x * 256 + threadIdx.x;
    int row = tid >> 3;                 // global row in [0, NT4_)
    if (row >= NT4_) return;
    if (hop == 2 && !g_mask[row]) return;
    int k = tid & 7;
    const __nv_bfloat16* xg = (hop == 0) ? g_Xh : ((hop == 1) ? g_B1 : g_B2);
    __nv_bfloat16* y = (hop == 0) ? g_B1 : ((hop == 1) ? g_B2 : g_B3);
    int l = row / NT_;
    const __nv_bfloat16* xb = xg + (size_t)l * NT_ * D_;
    int s0 = g_rowptr[row];
    int s1 = g_rowptr[row + 1];
    float s[8] = {0.f, 0.f, 0.f, 0.f, 0.f, 0.f, 0.f, 0.f};
#pragma unroll 8
    for (int e = s0; e < s1; e++) {
        int2 ed = __ldcs(&g_edges[e]);  // uniform in 8-lane group -> broadcast
        float vj = __int_as_float(ed.y);
        uint4 raw = *(const uint4*)(xb + ed.x * D_ + k * 8);
        const __nv_bfloat162* p = (const __nv_bfloat162*)&raw;
#pragma unroll
        for (int q = 0; q < 4; q++) {
            float2 f = __bfloat1622float2(p[q]);
            s[q * 2]     += vj * f.x;
            s[q * 2 + 1] += vj * f.y;
        }
    }
    size_t ro = (size_t)row * D_ + k * 8;
    // residual: + h[row]
    {
        uint4 raw = *(const uint4*)(xg + ro);
        const __nv_bfloat162* p = (const __nv_bfloat162*)&raw;
#pragma unroll
        for (int q = 0; q < 4; q++) {
            float2 f = __bfloat1622float2(p[q]);
            s[q * 2]     += f.x;
            s[q * 2 + 1] += f.y;
        }
    }
    // store y (bf16)
    __nv_bfloat162 h[4];
#pragma unroll
    for (int q = 0; q < 4; q++)
        h[q] = __float22bfloat162_rn(make_float2(s[q * 2], s[q * 2 + 1]));
    *(uint4*)(y + ro) = *(uint4*)h;
}

// ---------------------------------------------------------------------------
// Loss kernels: reconstruct 0.25*(h0+h1+h2+h3) on the fly.

__global__ void __launch_bounds__(256) k_rating(const int* __restrict__ user,
                                                const int* __restrict__ pos,
                                                const int* __restrict__ neg,
                                                const float* __restrict__ ue,
                                                const float* __restrict__ ie) {
    int gt = blockIdx.x * 256 + threadIdx.x;
    int w = gt >> 5, lane = gt & 31;
    if (w >= 8192) return;
    int ur = user[w];
    int pr = pos[w];
    int nr = neg[w];
    float pp = 0.f, np = 0.f, l2 = 0.f;
#pragma unroll
    for (int q = 0; q < 2; q++) {
        int d = lane * 2 + q;
        float u = acc4_(ue, ur, ur, d);                  // layer 0, user
        float a = acc4_(ie, pr, (size_t)NU_ + pr, d);    // layer 0, item
        float b = acc4_(ie, nr, (size_t)NU_ + nr, d);
        pp += u * a;
        np += u * b;
        l2 += u * u + a * a + b * b;
    }
    for (int o = 16; o; o >>= 1) {
        pp += __shfl_down_sync(0xffffffffu, pp, o);
        np += __shfl_down_sync(0xffffffffu, np, o);
        l2 += __shfl_down_sync(0xffffffffu, l2, o);
    }
    if (lane == 0) atomicAdd(&g_scal[0], sp_(np - pp) + 0.01f * l2);
}

// Sum of -softplus(sign*acc) over 4096 gathered user rows of layer at rowoff.
__global__ void __launch_bounds__(256) k_brilog(const int* __restrict__ idx,
                                                const float* __restrict__ emb,
                                                int rowoff, float sign, int slot) {
    int t = blockIdx.x * 256 + threadIdx.x;  // exactly 4096*64 threads
    int i = t >> 6, d = t & 63;
    int r = idx[i];
    float x = acc4_(emb, r, (size_t)rowoff + r, d);
    float val = -sp_(sign * x);
    __shared__ float sm[256];
    sm[threadIdx.x] = val;
    __syncthreads();
    for (int s = 128; s; s >>= 1) {
        if (threadIdx.x < s) sm[threadIdx.x] += sm[threadIdx.x + s];
        __syncthreads();
    }
    if (threadIdx.x == 0) atomicAdd(&g_scal[slot], sm[0]);
}

// Column sums of acc over layer-2 user rows [BRI_, BRI_+50000) -> g_scal[8+d].
__global__ void __launch_bounds__(256) k_gsoc(const float* __restrict__ sgu) {
    int gt = blockIdx.x * 256 + threadIdx.x;  // 128 blocks -> 512 row groups
    int d = gt & 63;
    int rg = gt >> 6;
    const size_t base = (size_t)2 * NT_;  // layer 2 global row offset
    float s = 0.f;
    for (int r = BRI_ + rg; r < BRI_ + 50000; r += 512)
        s += acc4_(sgu, r, base + r, d);
    __shared__ float sm[256];
    sm[threadIdx.x] = s;
    __syncthreads();
    if (threadIdx.x < 64)
        atomicAdd(&g_scal[8 + threadIdx.x],
                  sm[threadIdx.x] + sm[threadIdx.x + 64] +
                  sm[threadIdx.x + 128] + sm[threadIdx.x + 192]);
}

// Column sums of sigmoid(acc) over 4096 gathered rows -> g_scal[slot+d].
__global__ void __launch_bounds__(256) k_gmean(const int* __restrict__ idx,
                                               const float* __restrict__ emb,
                                               int growoff, int slot) {
    int t = blockIdx.x * 256 + threadIdx.x;  // exactly 4096*64 threads
    int i = t >> 6, d = t & 63;
    int r = idx[i];
    float x = acc4_(emb, r, (size_t)growoff + r, d);
    float sg = 1.f / (1.f + expf(-x));
    __shared__ float sm[256];
    sm[threadIdx.x] = sg;
    __syncthreads();
    if (threadIdx.x < 64)
        atomicAdd(&g_scal[slot + threadIdx.x],
                  sm[threadIdx.x] + sm[threadIdx.x + 64] +
                  sm[threadIdx.x + 128] + sm[threadIdx.x + 192]);
}

__global__ void k_final(float* __restrict__ out) {
    double sgr = 0.0, sgf = 0.0, sir = 0.0, sif = 0.0;
    for (int d = 0; d < 64; d++) {
        double gs = (double)g_scal[8 + d] / 50000.0;
        double sg = 1.0 / (1.0 + exp(-gs));
        sgr += log(sg);
        sgf += log(1.0 - sg);
    }
    for (int d = 0; d < 128; d++) {
        double g = (double)g_scal[72 + d] / 4096.0;
        sir += log(g);
        sif += log1p(-g);
    }
    double A1 = g_scal[0], A2 = g_scal[1], A3 = g_scal[2];
    double A5 = g_scal[3], A6 = g_scal[4];
    double social = -(A2 / (4096.0 * 128.0) + sgr / 128.0)
                    - (A3 / (4096.0 * 128.0) + sgf / 128.0);
    double infor  = -(A5 / (4096.0 * 192.0) + sir / 192.0)
                    - (A6 / (4096.0 * 192.0) + sif / 192.0);
    double rating = A1;
    double obj = rating + 100.0 * social + 1000.0 * infor;
    out[0] = (float)obj;
    out[1] = (float)rating;
    out[2] = (float)social;
    out[3] = (float)infor;
}

extern "C" void kernel_launch(void* const* d_in, const int* in_sizes, int n_in,
                              void* d_out, int out_size) {
    Ptrs P;
    for (int i = 0; i < 26; i++) P.p[i] = d_in[i];
    const float* ue  = (const float*)d_in[0];
    const float* ie  = (const float*)d_in[1];
    const float* fue = (const float*)d_in[2];
    const float* sgu = (const float*)d_in[4];
    const float* igu = (const float*)d_in[6];
    const float* igi = (const float*)d_in[7];
    const int* user      = (const int*)d_in[20];
    const int* pos       = (const int*)d_in[21];
    const int* neg       = (const int*)d_in[22];
    const int* s_bri     = (const int*)d_in[23];
    const int* i_bri     = (const int*)d_in[24];
    const int* i_bri_pos = (const int*)d_in[25];

    k_setup<<<1, 256>>>((const unsigned*)d_in[8]);

    const int CHG4 = (NT4_ * D_ / 8 + 255) / 256;  // 18750
    const int EDG4 = (NNZ4_ + 255) / 256;          // 37500
    const int SPG4 = (NT4_ * 8 + 255) / 256;       // 18750

    k_init<<<CHG4, 256>>>(P);
    k_mark<<<(99152 + 255) / 256, 256>>>(user, pos, neg, s_bri, i_bri, i_bri_pos);
    k_hist<<<EDG4, 256>>>(P);
    k_scanA<<<SCB4_, 1024>>>();
    k_scanB<<<1, 1024>>>();
    k_scanC<<<SCB4_, 1024>>>();
    k_scatter<<<EDG4, 256>>>(P);
    for (int hop = 0; hop < 3; hop++)
        k_spmm_csr<<<SPG4, 256>>>(hop);

    k_rating<<<1024, 256>>>(user, pos, neg, ue, ie);
    k_brilog<<<1024, 256>>>(s_bri, ue, 0, -1.f, 1);               // layer 0
    k_brilog<<<1024, 256>>>(i_bri, ue, 0, -1.f, 3);               // layer 0
    k_brilog<<<1024, 256>>>(s_bri, fue, NT_, 1.f, 2);             // layer 1
    k_brilog<<<1024, 256>>>(i_bri, fue, NT_, 1.f, 4);             // layer 1
    k_gsoc<<<128, 256>>>(sgu);                                    // layer 2
    k_gmean<<<1024, 256>>>(i_bri, igu, 3 * NT_, 72);              // layer 3 users
    k_gmean<<<1024, 256>>>(i_bri_pos, igi, 3 * NT_ + NU_, 136);   // layer 3 items
    k_final<<<1, 1>>>((float*)d_out);
}